// round 4
// baseline (speedup 1.0000x reference)
#include <cuda_runtime.h>
#include <cuda_bf16.h>
#include <cstdint>
#include <math.h>

#define NB 32
#define NS 64
#define NH 512
#define NA 128
#define NWIN 2016
#define NWPAD 2048
#define NLEV 7
#define MT 128          // windows per CTA tile
#define KT 32           // K per k-tile
#define NKT (NH / KT)   // 16 k-tiles
#define LDS_A 40        // padded row stride (bf16) -> 80B
#define STAGE_BYTES 40960   // 4 arrays * 128 * 80B
#define AHI_OFF 0
#define ALO_OFF 10240
#define BHI_OFF 20480
#define BLO_OFF 30720

// Scratch (static device globals — no allocation).
__device__ float g_table[NLEV * NB * NS * NH];   // ~29.4 MB
__device__ float g_scores[NB * NWPAD];
__device__ int   g_win[NWPAD];                   // packed: s | e2<<8 | k<<16
__device__ __nv_bfloat16 g_w1t_hi[NA * NH];      // W1^T bf16 hi, [n][k]
__device__ __nv_bfloat16 g_w1t_lo[NA * NH];      // W1^T bf16 lo

// ---------------------------------------------------------------------------
__device__ __forceinline__ uint32_t smem_u32(const void* p) {
    uint32_t a;
    asm("{ .reg .u64 t; cvta.to.shared.u64 t, %1; cvt.u32.u64 %0, t; }" : "=r"(a) : "l"(p));
    return a;
}
#define LDSM_X4(r0, r1, r2, r3, a) \
    asm volatile("ldmatrix.sync.aligned.m8n8.x4.shared.b16 {%0,%1,%2,%3}, [%4];" \
        : "=r"(r0), "=r"(r1), "=r"(r2), "=r"(r3) : "r"(a))
#define CP_ASYNC16(dst, src) \
    asm volatile("cp.async.ca.shared.global [%0], [%1], 16;" :: "r"(dst), "l"(src))
#define CP_COMMIT() asm volatile("cp.async.commit_group;" ::: "memory")
#define CP_WAIT(n)  asm volatile("cp.async.wait_group %0;" :: "n"(n) : "memory")

__device__ __forceinline__ void mma_bf16(float* c, const uint32_t* a, const uint32_t* b) {
    asm volatile(
        "mma.sync.aligned.m16n8k16.row.col.f32.bf16.bf16.f32 "
        "{%0,%1,%2,%3}, {%4,%5,%6,%7}, {%8,%9}, {%0,%1,%2,%3};"
        : "+f"(c[0]), "+f"(c[1]), "+f"(c[2]), "+f"(c[3])
        : "r"(a[0]), "r"(a[1]), "r"(a[2]), "r"(a[3]), "r"(b[0]), "r"(b[1]));
}

// truncation hi/lo split of 2 floats -> packed hi bf16x2, lo bf16x2
__device__ __forceinline__ void split2(float a, float b, uint32_t& hi, uint32_t& lo) {
    uint32_t ua = __float_as_uint(a), ub = __float_as_uint(b);
    hi = __byte_perm(ua, ub, 0x7632);
    float la = a - __uint_as_float(ua & 0xffff0000u);
    float lb = b - __uint_as_float(ub & 0xffff0000u);
    __nv_bfloat162 p = __floats2bfloat162_rn(la, lb);
    lo = *(uint32_t*)&p;
}

// ---------------------------------------------------------------------------
// Prep kernel: grid (8, NB+2).
//   by <  NB : sparse max-table build (h-chunk of 64 per bx)
//   by == NB : window index table
//   by == NB+1 : W1^T bf16 hi/lo precompute
__global__ void __launch_bounds__(256) k_prep(const float* __restrict__ lstm,
                                              const float* __restrict__ W1) {
    int tid = threadIdx.x;
    int by = blockIdx.y, bx = blockIdx.x;

    if (by < NB) {
        int b = by, h0 = bx * 64;
        __shared__ float buf[2][NS][64];
        for (int idx = tid; idx < NS * 64; idx += 256) {
            int i = idx >> 6, h = idx & 63;
            float v = lstm[(b * NS + i) * NH + h0 + h];
            buf[0][i][h] = v;
            g_table[((size_t)(0 * NB + b) * NS + i) * NH + h0 + h] = v;
        }
        __syncthreads();
        int cur = 0;
        for (int k = 1; k < NLEV; k++) {
            int half = 1 << (k - 1);
            int nxt = cur ^ 1;
            for (int idx = tid; idx < NS * 64; idx += 256) {
                int i = idx >> 6, h = idx & 63;
                float v = buf[cur][i][h];
                if (i + half < NS) v = fmaxf(v, buf[cur][i + half][h]);
                buf[nxt][i][h] = v;
                g_table[((size_t)(k * NB + b) * NS + i) * NH + h0 + h] = v;
            }
            __syncthreads();
            cur = nxt;
        }
    } else if (by == NB) {
        int n = bx * 256 + tid;
        if (n >= NWPAD) return;
        int nn = n < NWIN ? n : NWIN - 1;
        int w = 2;
#pragma unroll 1
        for (int ww = 3; ww <= NS; ww++) {
            int F = (129 - ww) * (ww - 2) / 2;
            if (F <= nn) w = ww;
        }
        int Fw = (129 - w) * (w - 2) / 2;
        int s = nn - Fw;
        int k = 31 - __clz(w);
        int e2 = s + w - (1 << k);
        g_win[n] = s | (e2 << 8) | (k << 16);
    } else {
        // W1^T split: each thread handles 32 consecutive k for one n.
        int t = bx * 256 + tid;          // 0..2047
        int n = t >> 3;                  // 0..255?? -> need 128 rows * 16 thr
        int kc = (t & 7) * 64;           // 64 k per thread
        if (n >= NA) return;
#pragma unroll 4
        for (int k = kc; k < kc + 64; k++) {
            float v = W1[k * NA + n];
            uint32_t u = __float_as_uint(v);
            g_w1t_hi[n * NH + k] = __ushort_as_bfloat16((unsigned short)(u >> 16));
            float lv = v - __uint_as_float(u & 0xffff0000u);
            g_w1t_lo[n * NH + k] = __float2bfloat16(lv);
        }
    }
}

// ---------------------------------------------------------------------------
// Pipelined bf16 mma.sync score kernel. CTA: 128 win x 128 ATT, 512 threads.
// Warp grid 4x4: warp tile 32x32. Double-buffered smem stages; B via cp.async.
__global__ void __launch_bounds__(512, 1) k_scores_mma(
    const float* __restrict__ b1, const float* __restrict__ W2)
{
    extern __shared__ __align__(128) char dyn[];
    __shared__ float sPart[4][MT];
    __shared__ float sb1[NA], sw2[NA];
    __shared__ int s_win[MT];

    int b  = blockIdx.y;
    int n0 = blockIdx.x * MT;
    int tid  = threadIdx.x;
    int wid  = tid >> 5, lane = tid & 31;
    int wm = wid & 3, wn = wid >> 2;      // 4 x 4 warp grid

    if (tid < MT) {
        int n = n0 + tid;
        s_win[tid] = g_win[n < NWIN ? n : NWIN - 1];
    }
    if (tid >= MT && tid < MT + NA) { int a = tid - MT; sb1[a] = b1[a]; sw2[a] = W2[a]; }

    float acc[2][4][4];
#pragma unroll
    for (int mt = 0; mt < 2; mt++)
#pragma unroll
        for (int nt = 0; nt < 4; nt++)
#pragma unroll
            for (int j = 0; j < 4; j++) acc[mt][nt][j] = 0.f;

    uint32_t dynB = smem_u32(dyn);

    // per-thread A-gather geometry: row m, 8-col chunk c0
    int am = tid >> 2;
    int ac0 = (tid & 3) * 8;
    // B cp.async geometry: row n, 16B chunk
    int bn = tid >> 2;
    int bch = tid & 3;
    const char* w1hiP = (const char*)g_w1t_hi + (size_t)bn * (NH * 2) + bch * 16;
    const char* w1loP = (const char*)g_w1t_lo + (size_t)bn * (NH * 2) + bch * 16;

    __syncthreads();   // s_win ready

    uint4 rhA, rlA;    // gathered A regs for next stage

    // ---- gather A for tile t into regs
    auto gatherA = [&](int t, uint4& rh, uint4& rl) {
        int wi = s_win[am];
        int s = wi & 255, e2 = (wi >> 8) & 255, k = wi >> 16;
        const float* base = g_table + ((size_t)(k * NB + b) * NS) * NH + t * KT + ac0;
        float4 x0 = *(const float4*)(base + (size_t)s * NH);
        float4 x1 = *(const float4*)(base + (size_t)s * NH + 4);
        float4 y0 = *(const float4*)(base + (size_t)e2 * NH);
        float4 y1 = *(const float4*)(base + (size_t)e2 * NH + 4);
        float v0 = fmaxf(x0.x, y0.x), v1 = fmaxf(x0.y, y0.y);
        float v2 = fmaxf(x0.z, y0.z), v3 = fmaxf(x0.w, y0.w);
        float v4 = fmaxf(x1.x, y1.x), v5 = fmaxf(x1.y, y1.y);
        float v6 = fmaxf(x1.z, y1.z), v7 = fmaxf(x1.w, y1.w);
        split2(v0, v1, rh.x, rl.x);
        split2(v2, v3, rh.y, rl.y);
        split2(v4, v5, rh.z, rl.z);
        split2(v6, v7, rh.w, rl.w);
    };
    auto stsA = [&](int stage, const uint4& rh, const uint4& rl) {
        uint32_t off = (uint32_t)stage * STAGE_BYTES + (uint32_t)am * 80 + (uint32_t)ac0 * 2;
        *(uint4*)(dyn + AHI_OFF + off) = rh;
        *(uint4*)(dyn + ALO_OFF + off) = rl;
    };
    auto issueB = [&](int t, int stage) {
        uint32_t dst = dynB + (uint32_t)stage * STAGE_BYTES + (uint32_t)bn * 80 + (uint32_t)bch * 16;
        CP_ASYNC16(dst + BHI_OFF, w1hiP + t * (KT * 2));
        CP_ASYNC16(dst + BLO_OFF, w1loP + t * (KT * 2));
        CP_COMMIT();
    };

    // prologue: stage 0
    gatherA(0, rhA, rlA);
    stsA(0, rhA, rlA);
    issueB(0, 0);

    // ldmatrix lane addressing
    uint32_t aRow = (uint32_t)(lane & 15);
    uint32_t aCol = (uint32_t)(lane >> 4) * 16u;
    uint32_t bRow = (uint32_t)((lane & 7) + ((lane >> 4) << 3));
    uint32_t bCol = (uint32_t)((lane >> 3) & 1) * 16u;

    for (int t = 0; t < NKT; t++) {
        int cur = t & 1, nxt = cur ^ 1;
        bool more = (t + 1 < NKT);
        if (more) {
            gatherA(t + 1, rhA, rlA);   // LDGs in flight under MMA
            issueB(t + 1, nxt);
            CP_WAIT(1);
        } else {
            CP_WAIT(0);
        }
        __syncthreads();   // stage cur fully visible

        uint32_t aHiB = dynB + (uint32_t)cur * STAGE_BYTES + AHI_OFF;
        uint32_t aLoB = dynB + (uint32_t)cur * STAGE_BYTES + ALO_OFF;
        uint32_t bHiB = dynB + (uint32_t)cur * STAGE_BYTES + BHI_OFF;
        uint32_t bLoB = dynB + (uint32_t)cur * STAGE_BYTES + BLO_OFF;

#pragma unroll
        for (int ks = 0; ks < 2; ks++) {
            uint32_t kOff = (uint32_t)ks * 32u;
            uint32_t Ah[2][4], Al[2][4];
#pragma unroll
            for (int mt = 0; mt < 2; mt++) {
                uint32_t row = (uint32_t)(wm * 32 + mt * 16) + aRow;
                uint32_t off = row * (LDS_A * 2) + kOff + aCol;
                LDSM_X4(Ah[mt][0], Ah[mt][1], Ah[mt][2], Ah[mt][3], aHiB + off);
                LDSM_X4(Al[mt][0], Al[mt][1], Al[mt][2], Al[mt][3], aLoB + off);
            }
#pragma unroll
            for (int np = 0; np < 2; np++) {
                uint32_t nrow = (uint32_t)(wn * 32 + np * 16) + bRow;
                uint32_t off = nrow * (LDS_A * 2) + kOff + bCol;
                uint32_t Bh[4], Bl[4];
                LDSM_X4(Bh[0], Bh[1], Bh[2], Bh[3], bHiB + off);
                LDSM_X4(Bl[0], Bl[1], Bl[2], Bl[3], bLoB + off);
#pragma unroll
                for (int mt = 0; mt < 2; mt++) {
#pragma unroll
                    for (int h = 0; h < 2; h++) {
                        int nt = np * 2 + h;
                        mma_bf16(acc[mt][nt], Ah[mt], &Bh[h * 2]);
                        mma_bf16(acc[mt][nt], Ah[mt], &Bl[h * 2]);
                        mma_bf16(acc[mt][nt], Al[mt], &Bh[h * 2]);
                    }
                }
            }
        }
        if (more) stsA(nxt, rhA, rlA);
        __syncthreads();   // protect stage nxt (writes) / cur (reads) boundaries
    }

    // ---- epilogue: relu(acc + b1) dot W2, reduce over n
    int gq = lane >> 2;
    int gr = lane & 3;
#pragma unroll
    for (int mt = 0; mt < 2; mt++) {
        float p0 = 0.f, p1 = 0.f;
#pragma unroll
        for (int nt = 0; nt < 4; nt++) {
            int col = wn * 32 + nt * 8 + gr * 2;
            float b1a = sb1[col], b1b = sb1[col + 1];
            float w2a = sw2[col], w2b = sw2[col + 1];
            p0 = fmaf(fmaxf(acc[mt][nt][0] + b1a, 0.f), w2a, p0);
            p0 = fmaf(fmaxf(acc[mt][nt][1] + b1b, 0.f), w2b, p0);
            p1 = fmaf(fmaxf(acc[mt][nt][2] + b1a, 0.f), w2a, p1);
            p1 = fmaf(fmaxf(acc[mt][nt][3] + b1b, 0.f), w2b, p1);
        }
#pragma unroll
        for (int off = 1; off <= 2; off <<= 1) {
            p0 += __shfl_xor_sync(0xffffffffu, p0, off);
            p1 += __shfl_xor_sync(0xffffffffu, p1, off);
        }
        if (gr == 0) {
            int row = wm * 32 + mt * 16 + gq;
            sPart[wn][row]     = p0;
            sPart[wn][row + 8] = p1;
        }
    }
    __syncthreads();
    if (tid < MT) {
        int n = n0 + tid;
        if (n < NWIN)
            g_scores[b * NWPAD + n] =
                sPart[0][tid] + sPart[1][tid] + sPart[2][tid] + sPart[3][tid];
    }
}

// ---------------------------------------------------------------------------
// Fused softmax + weighted sum. grid (NH/128, NB), 128 threads.
__global__ void __launch_bounds__(128) k_out(float* __restrict__ out) {
    int b = blockIdx.y;
    int h = blockIdx.x * 128 + threadIdx.x;
    int tid = threadIdx.x;
    __shared__ float sattn[NWPAD];
    __shared__ int   swn[NWPAD];
    __shared__ float red[128];

    // softmax (unnormalized e; 1/sum folded at the end)
    float mx = -1e30f;
    for (int n = tid; n < NWIN; n += 128)
        mx = fmaxf(mx, g_scores[b * NWPAD + n]);
    red[tid] = mx;
    __syncthreads();
    for (int s = 64; s > 0; s >>= 1) {
        if (tid < s) red[tid] = fmaxf(red[tid], red[tid + s]);
        __syncthreads();
    }
    mx = red[0];
    __syncthreads();
    float sum = 0.f;
    for (int n = tid; n < NWIN; n += 128) {
        float e = __expf(g_scores[b * NWPAD + n] - mx);
        sattn[n] = e;
        swn[n] = g_win[n];
        sum += e;
    }
    red[tid] = sum;
    __syncthreads();
    for (int s = 64; s > 0; s >>= 1) {
        if (tid < s) red[tid] += red[tid + s];
        __syncthreads();
    }
    float inv = 1.f / red[0];
    __syncthreads();

    const float* tb = g_table + h;
    float acc = 0.f;
#pragma unroll 4
    for (int j = 0; j < NWIN; j++) {
        int wi = swn[j];
        int s = wi & 255, e2 = (wi >> 8) & 255, k = wi >> 16;
        const float* base = tb + (size_t)(k * NB + b) * NS * NH;
        acc += sattn[j] * fmaxf(base[s * NH], base[e2 * NH]);
    }
    out[b * NH + h] = acc * inv;
}

// ---------------------------------------------------------------------------
extern "C" void kernel_launch(void* const* d_in, const int* in_sizes, int n_in,
                              void* d_out, int out_size) {
    const float* lstm = (const float*)d_in[0];
    const float* W1   = (const float*)d_in[1];
    const float* b1   = (const float*)d_in[2];
    const float* W2   = (const float*)d_in[3];
    float* out = (float*)d_out;

    const int DYN = 2 * STAGE_BYTES;
    cudaFuncSetAttribute(k_scores_mma, cudaFuncAttributeMaxDynamicSharedMemorySize, DYN);

    k_prep<<<dim3(8, NB + 2), 256>>>(lstm, W1);
    k_scores_mma<<<dim3(NWPAD / MT, NB), 512, DYN>>>(b1, W2);
    k_out<<<dim3(NH / 128, NB), 128>>>(out);
}

// round 6
// speedup vs baseline: 1.0052x; 1.0052x over previous
#include <cuda_runtime.h>
#include <cuda_bf16.h>
#include <cstdint>
#include <math.h>

#define NB 32
#define NS 64
#define NH 512
#define NA 128
#define NWIN 2016
#define NWPAD 2048
#define NLEV 7          // levels 1..6 stored (level 0 never used: width>=2)
#define MT 128          // windows per CTA tile
#define KT 32           // K per k-tile
#define NKT (NH / KT)   // 16 k-tiles
#define LDS_A 40        // padded row stride (bf16) -> 80B

// Scratch (static device globals — no allocation).
__device__ float g_table[(NLEV - 1) * NB * NS * NH];   // levels 1..6, 25.2 MB
__device__ float g_scores[NB * NWPAD];
__device__ int   g_win[NWPAD];                   // packed: s | e2<<8 | k<<16
__device__ __nv_bfloat16 g_w1t_hi[NA * NH];      // W1^T bf16 hi, [n][k]
__device__ __nv_bfloat16 g_w1t_lo[NA * NH];      // W1^T bf16 lo

// ---------------------------------------------------------------------------
__device__ __forceinline__ uint32_t smem_u32(const void* p) {
    uint32_t a;
    asm("{ .reg .u64 t; cvta.to.shared.u64 t, %1; cvt.u32.u64 %0, t; }" : "=r"(a) : "l"(p));
    return a;
}
#define LDSM_X4(r0, r1, r2, r3, a) \
    asm volatile("ldmatrix.sync.aligned.m8n8.x4.shared.b16 {%0,%1,%2,%3}, [%4];" \
        : "=r"(r0), "=r"(r1), "=r"(r2), "=r"(r3) : "r"(a))
#define CP_ASYNC16(dst, src) \
    asm volatile("cp.async.ca.shared.global [%0], [%1], 16;" :: "r"(dst), "l"(src))
#define CP_COMMIT() asm volatile("cp.async.commit_group;" ::: "memory")
#define CP_WAIT0()  asm volatile("cp.async.wait_group 0;" ::: "memory")

__device__ __forceinline__ void mma_bf16(float* c, const uint32_t* a, const uint32_t* b) {
    asm volatile(
        "mma.sync.aligned.m16n8k16.row.col.f32.bf16.bf16.f32 "
        "{%0,%1,%2,%3}, {%4,%5,%6,%7}, {%8,%9}, {%0,%1,%2,%3};"
        : "+f"(c[0]), "+f"(c[1]), "+f"(c[2]), "+f"(c[3])
        : "r"(a[0]), "r"(a[1]), "r"(a[2]), "r"(a[3]), "r"(b[0]), "r"(b[1]));
}

// truncation hi/lo split of 2 floats -> packed hi bf16x2, lo bf16x2
__device__ __forceinline__ void split2(float a, float b, uint32_t& hi, uint32_t& lo) {
    uint32_t ua = __float_as_uint(a), ub = __float_as_uint(b);
    hi = __byte_perm(ua, ub, 0x7632);
    float la = a - __uint_as_float(ua & 0xffff0000u);
    float lb = b - __uint_as_float(ub & 0xffff0000u);
    __nv_bfloat162 p = __floats2bfloat162_rn(la, lb);
    lo = *(uint32_t*)&p;
}

__device__ __forceinline__ float4 f4max(float4 a, float4 b) {
    return make_float4(fmaxf(a.x, b.x), fmaxf(a.y, b.y), fmaxf(a.z, b.z), fmaxf(a.w, b.w));
}

// ---------------------------------------------------------------------------
// Prep kernel: grid (8, NB+2), 256 threads.
__global__ void __launch_bounds__(256) k_prep(const float* __restrict__ lstm,
                                              const float* __restrict__ W1) {
    int tid = threadIdx.x;
    int by = blockIdx.y, bx = blockIdx.x;

    if (by < NB) {
        int b = by, h0 = bx * 64;
        __shared__ float4 buf[2][NS][16];          // 64 i x 64 h (16 float4)
        int i = tid & 63, hq = tid >> 6;           // hq in 0..3
#pragma unroll
        for (int c = 0; c < 4; c++) {
            int q = hq * 4 + c;
            buf[0][i][q] = *(const float4*)(lstm + ((size_t)(b * NS + i)) * NH + h0 + q * 4);
        }
        __syncthreads();
        int cur = 0;
        for (int k = 1; k < NLEV; k++) {
            int half = 1 << (k - 1);
            int nxt = cur ^ 1;
            float4* dst = (float4*)(g_table + ((size_t)((k - 1) * NB + b) * NS + i) * NH + h0);
#pragma unroll
            for (int c = 0; c < 4; c++) {
                int q = hq * 4 + c;
                float4 v = buf[cur][i][q];
                if (i + half < NS) v = f4max(v, buf[cur][i + half][q]);
                buf[nxt][i][q] = v;
                dst[q] = v;
            }
            __syncthreads();
            cur = nxt;
        }
    } else if (by == NB) {
        int n = bx * 256 + tid;
        if (n >= NWPAD) return;
        int nn = n < NWIN ? n : NWIN - 1;
        int w = 2;
#pragma unroll 1
        for (int ww = 3; ww <= NS; ww++) {
            int F = (129 - ww) * (ww - 2) / 2;
            if (F <= nn) w = ww;
        }
        int Fw = (129 - w) * (w - 2) / 2;
        int s = nn - Fw;
        int k = 31 - __clz(w);
        int e2 = s + w - (1 << k);
        g_win[n] = s | (e2 << 8) | (k << 16);
    } else {
        int t = bx * 256 + tid;          // 0..2047
        int n = t >> 3;
        int kc = (t & 7) * 64;
        if (n >= NA) return;
#pragma unroll 4
        for (int k = kc; k < kc + 64; k++) {
            float v = W1[k * NA + n];
            uint32_t u = __float_as_uint(v);
            g_w1t_hi[n * NH + k] = __ushort_as_bfloat16((unsigned short)(u >> 16));
            float lv = v - __uint_as_float(u & 0xffff0000u);
            g_w1t_lo[n * NH + k] = __float2bfloat16(lv);
        }
    }
}

// ---------------------------------------------------------------------------
// Score kernel: 256 thr, single buffer, occ 2. CTA: 128 win x 128 ATT,
// warp grid 4x2 (warp tile 32x64), K=512 in 16 tiles of 32.
__global__ void __launch_bounds__(256, 2) k_scores_mma(
    const float* __restrict__ b1, const float* __restrict__ W2)
{
    __shared__ __align__(16) __nv_bfloat16 aHi[MT][LDS_A];
    __shared__ __align__(16) __nv_bfloat16 aLo[MT][LDS_A];
    __shared__ __align__(16) __nv_bfloat16 bHi[NA][LDS_A];
    __shared__ __align__(16) __nv_bfloat16 bLo[NA][LDS_A];
    __shared__ float sPart[2][MT];
    __shared__ float sb1[NA], sw2[NA];
    __shared__ int s_win[MT];

    int b  = blockIdx.y;
    int n0 = blockIdx.x * MT;
    int tid  = threadIdx.x;
    int wid  = tid >> 5, lane = tid & 31;
    int wm = wid & 3, wn = wid >> 2;      // 4 x 2 warp grid

    if (tid < MT) {
        int n = n0 + tid;
        s_win[tid] = g_win[n < NWIN ? n : NWIN - 1];
    }
    if (tid >= MT && tid < MT + NA) { int a = tid - MT; sb1[a] = b1[a]; sw2[a] = W2[a]; }

    float acc[2][8][4];
#pragma unroll
    for (int mt = 0; mt < 2; mt++)
#pragma unroll
        for (int nt = 0; nt < 8; nt++)
#pragma unroll
            for (int j = 0; j < 4; j++) acc[mt][nt][j] = 0.f;

    // A-gather geometry: m = tid>>1, 16-col half = (tid&1)*16  (covers KT=32)
    int am = tid >> 1;
    int ac0 = (tid & 1) * 16;
    // B cp.async geometry: n = tid>>1, two 16B chunks at (tid&1)*32
    int bn = tid >> 1;
    int bco = (tid & 1) * 32;
    const char* w1hiP = (const char*)g_w1t_hi + (size_t)bn * (NH * 2) + bco;
    const char* w1loP = (const char*)g_w1t_lo + (size_t)bn * (NH * 2) + bco;
    uint32_t bHiDst = smem_u32(&bHi[bn][0]) + bco;
    uint32_t bLoDst = smem_u32(&bLo[bn][0]) + bco;

    __syncthreads();   // s_win ready

    uint32_t aRow = (uint32_t)(lane & 15);
    uint32_t aCol = (uint32_t)(lane >> 4) * 16u;
    uint32_t bRow = (uint32_t)((lane & 7) + ((lane >> 4) << 3));
    uint32_t bCol = (uint32_t)((lane >> 3) & 1) * 16u;
    uint32_t aHiBase = smem_u32(&aHi[0][0]), aLoBase = smem_u32(&aLo[0][0]);
    uint32_t bHiBase = smem_u32(&bHi[0][0]), bLoBase = smem_u32(&bLo[0][0]);

    // per-thread window (constant across tiles)
    int wi = s_win[am];
    int ws = wi & 255, we2 = (wi >> 8) & 255, wk = wi >> 16;
    const float* gbase = g_table + ((size_t)((wk - 1) * NB + b) * NS) * NH + ac0;

    for (int t = 0; t < NKT; t++) {
        int th0 = t * KT;
        // B: 4 cp.async of 16B (pre-converted, k-contiguous)
        CP_ASYNC16(bHiDst,      w1hiP + t * (KT * 2));
        CP_ASYNC16(bHiDst + 16, w1hiP + t * (KT * 2) + 16);
        CP_ASYNC16(bLoDst,      w1loP + t * (KT * 2));
        CP_ASYNC16(bLoDst + 16, w1loP + t * (KT * 2) + 16);
        CP_COMMIT();

        // A: gather 16 floats (4x float4 per row), split, 2x STS.128 per array
        {
            const float* ps = gbase + th0 + (size_t)ws * NH;
            const float* pe = gbase + th0 + (size_t)we2 * NH;
            float4 v0 = f4max(*(const float4*)(ps),      *(const float4*)(pe));
            float4 v1 = f4max(*(const float4*)(ps + 4),  *(const float4*)(pe + 4));
            float4 v2 = f4max(*(const float4*)(ps + 8),  *(const float4*)(pe + 8));
            float4 v3 = f4max(*(const float4*)(ps + 12), *(const float4*)(pe + 12));
            uint4 rh0, rl0, rh1, rl1;
            split2(v0.x, v0.y, rh0.x, rl0.x);
            split2(v0.z, v0.w, rh0.y, rl0.y);
            split2(v1.x, v1.y, rh0.z, rl0.z);
            split2(v1.z, v1.w, rh0.w, rl0.w);
            split2(v2.x, v2.y, rh1.x, rl1.x);
            split2(v2.z, v2.w, rh1.y, rl1.y);
            split2(v3.x, v3.y, rh1.z, rl1.z);
            split2(v3.z, v3.w, rh1.w, rl1.w);
            *(uint4*)&aHi[am][ac0]     = rh0;
            *(uint4*)&aHi[am][ac0 + 8] = rh1;
            *(uint4*)&aLo[am][ac0]     = rl0;
            *(uint4*)&aLo[am][ac0 + 8] = rl1;
        }
        CP_WAIT0();
        __syncthreads();

        // ---- compute: 2 k-steps of 16
#pragma unroll
        for (int ks = 0; ks < 2; ks++) {
            uint32_t kOff = (uint32_t)ks * 32u;
            uint32_t Ah[2][4], Al[2][4];
#pragma unroll
            for (int mt = 0; mt < 2; mt++) {
                uint32_t row = (uint32_t)(wm * 32 + mt * 16) + aRow;
                uint32_t off = row * (LDS_A * 2) + kOff + aCol;
                LDSM_X4(Ah[mt][0], Ah[mt][1], Ah[mt][2], Ah[mt][3], aHiBase + off);
                LDSM_X4(Al[mt][0], Al[mt][1], Al[mt][2], Al[mt][3], aLoBase + off);
            }
#pragma unroll
            for (int np = 0; np < 4; np++) {
                uint32_t nrow = (uint32_t)(wn * 64 + np * 16) + bRow;
                uint32_t off = nrow * (LDS_A * 2) + kOff + bCol;
                uint32_t Bh[4], Bl[4];
                LDSM_X4(Bh[0], Bh[1], Bh[2], Bh[3], bHiBase + off);
                LDSM_X4(Bl[0], Bl[1], Bl[2], Bl[3], bLoBase + off);
#pragma unroll
                for (int mt = 0; mt < 2; mt++) {
#pragma unroll
                    for (int h = 0; h < 2; h++) {
                        int nt = np * 2 + h;
                        mma_bf16(acc[mt][nt], Ah[mt], &Bh[h * 2]);
                        mma_bf16(acc[mt][nt], Ah[mt], &Bl[h * 2]);
                        mma_bf16(acc[mt][nt], Al[mt], &Bh[h * 2]);
                    }
                }
            }
        }
        __syncthreads();
    }

    // ---- epilogue: relu(acc + b1) dot W2, reduce over n (b2 dropped: softmax-invariant)
    int gq = lane >> 2;
    int gr = lane & 3;
#pragma unroll
    for (int mt = 0; mt < 2; mt++) {
        float p0 = 0.f, p1 = 0.f;
#pragma unroll
        for (int nt = 0; nt < 8; nt++) {
            int col = wn * 64 + nt * 8 + gr * 2;
            float b1a = sb1[col], b1b = sb1[col + 1];
            float w2a = sw2[col], w2b = sw2[col + 1];
            p0 = fmaf(fmaxf(acc[mt][nt][0] + b1a, 0.f), w2a, p0);
            p0 = fmaf(fmaxf(acc[mt][nt][1] + b1b, 0.f), w2b, p0);
            p1 = fmaf(fmaxf(acc[mt][nt][2] + b1a, 0.f), w2a, p1);
            p1 = fmaf(fmaxf(acc[mt][nt][3] + b1b, 0.f), w2b, p1);
        }
#pragma unroll
        for (int off = 1; off <= 2; off <<= 1) {
            p0 += __shfl_xor_sync(0xffffffffu, p0, off);
            p1 += __shfl_xor_sync(0xffffffffu, p1, off);
        }
        if (gr == 0) {
            int row = wm * 32 + mt * 16 + gq;
            sPart[wn][row]     = p0;
            sPart[wn][row + 8] = p1;
        }
    }
    __syncthreads();
    if (tid < MT) {
        int n = n0 + tid;
        if (n < NWIN)
            g_scores[b * NWPAD + n] = sPart[0][tid] + sPart[1][tid];
    }
}

// ---------------------------------------------------------------------------
// Fused softmax + weighted sum. grid (NH/128, NB), 128 threads.
__global__ void __launch_bounds__(128) k_out(float* __restrict__ out) {
    int b = blockIdx.y;
    int h = blockIdx.x * 128 + threadIdx.x;
    int tid = threadIdx.x;
    __shared__ float sattn[NWPAD];
    __shared__ int   swn[NWPAD];
    __shared__ float red[128];

    float mx = -1e30f;
    for (int n = tid; n < NWIN; n += 128)
        mx = fmaxf(mx, g_scores[b * NWPAD + n]);
    red[tid] = mx;
    __syncthreads();
    for (int s = 64; s > 0; s >>= 1) {
        if (tid < s) red[tid] = fmaxf(red[tid], red[tid + s]);
        __syncthreads();
    }
    mx = red[0];
    __syncthreads();
    float sum = 0.f;
    for (int n = tid; n < NWIN; n += 128) {
        float e = __expf(g_scores[b * NWPAD + n] - mx);
        sattn[n] = e;
        swn[n] = g_win[n];
        sum += e;
    }
    red[tid] = sum;
    __syncthreads();
    for (int s = 64; s > 0; s >>= 1) {
        if (tid < s) red[tid] += red[tid + s];
        __syncthreads();
    }
    float inv = 1.f / red[0];
    __syncthreads();

    const float* tb = g_table + h;
    float acc = 0.f;
#pragma unroll 4
    for (int j = 0; j < NWIN; j++) {
        int wi = swn[j];
        int s = wi & 255, e2 = (wi >> 8) & 255, k = wi >> 16;
        const float* base = tb + (size_t)((k - 1) * NB + b) * NS * NH;
        acc += sattn[j] * fmaxf(base[s * NH], base[e2 * NH]);
    }
    out[b * NH + h] = acc * inv;
}

// ---------------------------------------------------------------------------
extern "C" void kernel_launch(void* const* d_in, const int* in_sizes, int n_in,
                              void* d_out, int out_size) {
    const float* lstm = (const float*)d_in[0];
    const float* W1   = (const float*)d_in[1];
    const float* b1   = (const float*)d_in[2];
    const float* W2   = (const float*)d_in[3];
    float* out = (float*)d_out;

    k_prep<<<dim3(8, NB + 2), 256>>>(lstm, W1);
    k_scores_mma<<<dim3(NWPAD / MT, NB), 256>>>(b1, W2);
    k_out<<<dim3(NH / 128, NB), 128>>>(out);
}

// round 7
// speedup vs baseline: 1.5078x; 1.5000x over previous
#include <cuda_runtime.h>
#include <cuda_bf16.h>
#include <cstdint>
#include <math.h>

#define NB 32
#define NS 64
#define NH 512
#define NA 128
#define NWIN 2016
#define NWPAD 2048
#define NLEV 7          // levels 1..6 stored (level 0 unused: width>=2)
#define MT 128
#define KT 32
#define NKT (NH / KT)
#define LDS_A 40        // padded row stride (bf16) -> 80B
#define NSEG 4
#define WSEG (NWIN / NSEG)   // 504

// Scratch (static device globals — no allocation).
__device__ float g_table[(NLEV - 1) * NB * NS * NH];   // levels 1..6, 25.2 MB
__device__ float g_scores[NB * NWPAD];
__device__ float g_partial[NSEG * NB * NH];
__device__ int   g_win[NWPAD];                   // packed: s | e2<<8 | k<<16
__device__ __nv_bfloat16 g_w1t_hi[NA * NH];      // W1^T bf16 hi, [n][k]
__device__ __nv_bfloat16 g_w1t_lo[NA * NH];      // W1^T bf16 lo

// ---------------------------------------------------------------------------
__device__ __forceinline__ uint32_t smem_u32(const void* p) {
    uint32_t a;
    asm("{ .reg .u64 t; cvta.to.shared.u64 t, %1; cvt.u32.u64 %0, t; }" : "=r"(a) : "l"(p));
    return a;
}
#define LDSM_X4(r0, r1, r2, r3, a) \
    asm volatile("ldmatrix.sync.aligned.m8n8.x4.shared.b16 {%0,%1,%2,%3}, [%4];" \
        : "=r"(r0), "=r"(r1), "=r"(r2), "=r"(r3) : "r"(a))
#define CP_ASYNC16(dst, src) \
    asm volatile("cp.async.ca.shared.global [%0], [%1], 16;" :: "r"(dst), "l"(src))
#define CP_COMMIT() asm volatile("cp.async.commit_group;" ::: "memory")
#define CP_WAIT1()  asm volatile("cp.async.wait_group 1;" ::: "memory")
#define CP_WAIT0()  asm volatile("cp.async.wait_group 0;" ::: "memory")

__device__ __forceinline__ void mma_bf16(float* c, const uint32_t* a, const uint32_t* b) {
    asm volatile(
        "mma.sync.aligned.m16n8k16.row.col.f32.bf16.bf16.f32 "
        "{%0,%1,%2,%3}, {%4,%5,%6,%7}, {%8,%9}, {%0,%1,%2,%3};"
        : "+f"(c[0]), "+f"(c[1]), "+f"(c[2]), "+f"(c[3])
        : "r"(a[0]), "r"(a[1]), "r"(a[2]), "r"(a[3]), "r"(b[0]), "r"(b[1]));
}

__device__ __forceinline__ void split2(float a, float b, uint32_t& hi, uint32_t& lo) {
    uint32_t ua = __float_as_uint(a), ub = __float_as_uint(b);
    hi = __byte_perm(ua, ub, 0x7632);
    float la = a - __uint_as_float(ua & 0xffff0000u);
    float lb = b - __uint_as_float(ub & 0xffff0000u);
    __nv_bfloat162 p = __floats2bfloat162_rn(la, lb);
    lo = *(uint32_t*)&p;
}

__device__ __forceinline__ float4 f4max(float4 a, float4 b) {
    return make_float4(fmaxf(a.x, b.x), fmaxf(a.y, b.y), fmaxf(a.z, b.z), fmaxf(a.w, b.w));
}

// ---------------------------------------------------------------------------
// Prep: grid (8, NB+2), 256 threads. Coalesced q-major float4 layout.
__global__ void __launch_bounds__(256) k_prep(const float* __restrict__ lstm,
                                              const float* __restrict__ W1) {
    int tid = threadIdx.x;
    int by = blockIdx.y, bx = blockIdx.x;

    if (by < NB) {
        int b = by, h0 = bx * 64;
        __shared__ float4 buf[2][NS][16];
        int q = tid & 15, i0 = tid >> 4;          // warp: 2 rows x 16 contiguous quads
#pragma unroll
        for (int c = 0; c < 4; c++) {
            int i = i0 + c * 16;
            buf[0][i][q] = *(const float4*)(lstm + ((size_t)(b * NS + i)) * NH + h0 + q * 4);
        }
        __syncthreads();
        int cur = 0;
        for (int k = 1; k < NLEV; k++) {
            int half = 1 << (k - 1);
            int nxt = cur ^ 1;
#pragma unroll
            for (int c = 0; c < 4; c++) {
                int i = i0 + c * 16;
                float4 v = buf[cur][i][q];
                if (i + half < NS) v = f4max(v, buf[cur][i + half][q]);
                buf[nxt][i][q] = v;
                *(float4*)(g_table + ((size_t)((k - 1) * NB + b) * NS + i) * NH + h0 + q * 4) = v;
            }
            __syncthreads();
            cur = nxt;
        }
    } else if (by == NB) {
        int n = bx * 256 + tid;
        if (n >= NWPAD) return;
        int nn = n < NWIN ? n : NWIN - 1;
        int w = 2;
#pragma unroll 1
        for (int ww = 3; ww <= NS; ww++) {
            int F = (129 - ww) * (ww - 2) / 2;
            if (F <= nn) w = ww;
        }
        int Fw = (129 - w) * (w - 2) / 2;
        int s = nn - Fw;
        int k = 31 - __clz(w);
        int e2 = s + w - (1 << k);
        g_win[n] = s | (e2 << 8) | (k << 16);
    } else {
        int t = bx * 256 + tid;
        int n = t >> 3;
        int kc = (t & 7) * 64;
        if (n >= NA) return;
#pragma unroll 4
        for (int k = kc; k < kc + 64; k++) {
            float v = W1[k * NA + n];
            uint32_t u = __float_as_uint(v);
            g_w1t_hi[n * NH + k] = __ushort_as_bfloat16((unsigned short)(u >> 16));
            float lv = v - __uint_as_float(u & 0xffff0000u);
            g_w1t_lo[n * NH + k] = __float2bfloat16(lv);
        }
    }
}

// ---------------------------------------------------------------------------
// Score kernel: 256 thr, occ 2. A single-stage, B double-stage cp.async,
// s-row gather prefetched into regs across the MMA section.
__global__ void __launch_bounds__(256, 2) k_scores_mma(
    const float* __restrict__ b1, const float* __restrict__ W2)
{
    __shared__ __align__(16) __nv_bfloat16 aHi[MT][LDS_A];
    __shared__ __align__(16) __nv_bfloat16 aLo[MT][LDS_A];
    __shared__ __align__(16) __nv_bfloat16 bHi[2][NA][LDS_A];
    __shared__ __align__(16) __nv_bfloat16 bLo[2][NA][LDS_A];
    __shared__ float sPart[2][MT];
    __shared__ float sb1[NA], sw2[NA];
    __shared__ int s_win[MT];

    int b  = blockIdx.y;
    int n0 = blockIdx.x * MT;
    int tid  = threadIdx.x;
    int wid  = tid >> 5, lane = tid & 31;
    int wm = wid & 3, wn = wid >> 2;

    if (tid < MT) {
        int n = n0 + tid;
        s_win[tid] = g_win[n < NWIN ? n : NWIN - 1];
    }
    if (tid >= MT && tid < MT + NA) { int a = tid - MT; sb1[a] = b1[a]; sw2[a] = W2[a]; }

    float acc[2][8][4];
#pragma unroll
    for (int mt = 0; mt < 2; mt++)
#pragma unroll
        for (int nt = 0; nt < 8; nt++)
#pragma unroll
            for (int j = 0; j < 4; j++) acc[mt][nt][j] = 0.f;

    int am = tid >> 1;
    int ac0 = (tid & 1) * 16;
    int bn = tid >> 1;
    int bco = (tid & 1) * 32;
    const char* w1hiP = (const char*)g_w1t_hi + (size_t)bn * (NH * 2) + bco;
    const char* w1loP = (const char*)g_w1t_lo + (size_t)bn * (NH * 2) + bco;
    uint32_t bHiD0 = smem_u32(&bHi[0][bn][0]) + bco;
    uint32_t bLoD0 = smem_u32(&bLo[0][bn][0]) + bco;
    const uint32_t stgStride = NA * LDS_A * 2;   // bytes per stage

    __syncthreads();   // s_win ready

    uint32_t aRow = (uint32_t)(lane & 15);
    uint32_t aCol = (uint32_t)(lane >> 4) * 16u;
    uint32_t bRow = (uint32_t)((lane & 7) + ((lane >> 4) << 3));
    uint32_t bCol = (uint32_t)((lane >> 3) & 1) * 16u;
    uint32_t aHiBase = smem_u32(&aHi[0][0]), aLoBase = smem_u32(&aLo[0][0]);
    uint32_t bHiBase = smem_u32(&bHi[0][0][0]), bLoBase = smem_u32(&bLo[0][0][0]);

    int wi = s_win[am];
    int ws = wi & 255, we2 = (wi >> 8) & 255, wk = wi >> 16;
    const float* gbase = g_table + ((size_t)((wk - 1) * NB + b) * NS) * NH + ac0;
    const float* sRowBase  = gbase + (size_t)ws * NH;
    const float* e2RowBase = gbase + (size_t)we2 * NH;

    // prologue: B(0) + s-row prefetch for t=0
    CP_ASYNC16(bHiD0,      w1hiP);
    CP_ASYNC16(bHiD0 + 16, w1hiP + 16);
    CP_ASYNC16(bLoD0,      w1loP);
    CP_ASYNC16(bLoD0 + 16, w1loP + 16);
    CP_COMMIT();
    float4 rs0 = *(const float4*)(sRowBase);
    float4 rs1 = *(const float4*)(sRowBase + 4);
    float4 rs2 = *(const float4*)(sRowBase + 8);
    float4 rs3 = *(const float4*)(sRowBase + 12);

    for (int t = 0; t < NKT; t++) {
        int cur = t & 1, nxt = cur ^ 1;
        bool more = (t + 1 < NKT);
        int th0 = t * KT;

        // A fill: prefetched s-row + fresh e2-row loads
        {
            const float* pe = e2RowBase + th0;
            float4 v0 = f4max(rs0, *(const float4*)(pe));
            float4 v1 = f4max(rs1, *(const float4*)(pe + 4));
            float4 v2 = f4max(rs2, *(const float4*)(pe + 8));
            float4 v3 = f4max(rs3, *(const float4*)(pe + 12));
            uint4 rh0, rl0, rh1, rl1;
            split2(v0.x, v0.y, rh0.x, rl0.x);
            split2(v0.z, v0.w, rh0.y, rl0.y);
            split2(v1.x, v1.y, rh0.z, rl0.z);
            split2(v1.z, v1.w, rh0.w, rl0.w);
            split2(v2.x, v2.y, rh1.x, rl1.x);
            split2(v2.z, v2.w, rh1.y, rl1.y);
            split2(v3.x, v3.y, rh1.z, rl1.z);
            split2(v3.z, v3.w, rh1.w, rl1.w);
            *(uint4*)&aHi[am][ac0]     = rh0;
            *(uint4*)&aHi[am][ac0 + 8] = rh1;
            *(uint4*)&aLo[am][ac0]     = rl0;
            *(uint4*)&aLo[am][ac0 + 8] = rl1;
        }
        // issue B(t+1) into stage nxt, then wait only for B(t)
        if (more) {
            const char* hp = w1hiP + (t + 1) * (KT * 2);
            const char* lp = w1loP + (t + 1) * (KT * 2);
            uint32_t hd = bHiD0 + (uint32_t)nxt * stgStride;
            uint32_t ld = bLoD0 + (uint32_t)nxt * stgStride;
            CP_ASYNC16(hd,      hp);
            CP_ASYNC16(hd + 16, hp + 16);
            CP_ASYNC16(ld,      lp);
            CP_ASYNC16(ld + 16, lp + 16);
            CP_COMMIT();
            CP_WAIT1();
        } else {
            CP_WAIT0();
        }
        __syncthreads();

        // prefetch s-row for t+1 (LDGs fly under the MMAs)
        if (more) {
            const float* ps = sRowBase + (t + 1) * KT;
            rs0 = *(const float4*)(ps);
            rs1 = *(const float4*)(ps + 4);
            rs2 = *(const float4*)(ps + 8);
            rs3 = *(const float4*)(ps + 12);
        }

        uint32_t bHiB = bHiBase + (uint32_t)cur * stgStride;
        uint32_t bLoB = bLoBase + (uint32_t)cur * stgStride;
#pragma unroll
        for (int ks = 0; ks < 2; ks++) {
            uint32_t kOff = (uint32_t)ks * 32u;
            uint32_t Ah[2][4], Al[2][4];
#pragma unroll
            for (int mt = 0; mt < 2; mt++) {
                uint32_t row = (uint32_t)(wm * 32 + mt * 16) + aRow;
                uint32_t off = row * (LDS_A * 2) + kOff + aCol;
                LDSM_X4(Ah[mt][0], Ah[mt][1], Ah[mt][2], Ah[mt][3], aHiBase + off);
                LDSM_X4(Al[mt][0], Al[mt][1], Al[mt][2], Al[mt][3], aLoBase + off);
            }
#pragma unroll
            for (int np = 0; np < 4; np++) {
                uint32_t nrow = (uint32_t)(wn * 64 + np * 16) + bRow;
                uint32_t off = nrow * (LDS_A * 2) + kOff + bCol;
                uint32_t Bh[4], Bl[4];
                LDSM_X4(Bh[0], Bh[1], Bh[2], Bh[3], bHiB + off);
                LDSM_X4(Bl[0], Bl[1], Bl[2], Bl[3], bLoB + off);
#pragma unroll
                for (int mt = 0; mt < 2; mt++) {
#pragma unroll
                    for (int h = 0; h < 2; h++) {
                        int nt = np * 2 + h;
                        mma_bf16(acc[mt][nt], Ah[mt], &Bh[h * 2]);
                        mma_bf16(acc[mt][nt], Ah[mt], &Bl[h * 2]);
                        mma_bf16(acc[mt][nt], Al[mt], &Bh[h * 2]);
                    }
                }
            }
        }
        __syncthreads();
    }

    // epilogue: relu(acc + b1) dot W2, reduce over n
    int gq = lane >> 2;
    int gr = lane & 3;
#pragma unroll
    for (int mt = 0; mt < 2; mt++) {
        float p0 = 0.f, p1 = 0.f;
#pragma unroll
        for (int nt = 0; nt < 8; nt++) {
            int col = wn * 64 + nt * 8 + gr * 2;
            float b1a = sb1[col], b1b = sb1[col + 1];
            float w2a = sw2[col], w2b = sw2[col + 1];
            p0 = fmaf(fmaxf(acc[mt][nt][0] + b1a, 0.f), w2a, p0);
            p0 = fmaf(fmaxf(acc[mt][nt][1] + b1b, 0.f), w2b, p0);
            p1 = fmaf(fmaxf(acc[mt][nt][2] + b1a, 0.f), w2a, p1);
            p1 = fmaf(fmaxf(acc[mt][nt][3] + b1b, 0.f), w2b, p1);
        }
#pragma unroll
        for (int off = 1; off <= 2; off <<= 1) {
            p0 += __shfl_xor_sync(0xffffffffu, p0, off);
            p1 += __shfl_xor_sync(0xffffffffu, p1, off);
        }
        if (gr == 0) {
            int row = wm * 32 + mt * 16 + gq;
            sPart[wn][row]     = p0;
            sPart[wn][row + 8] = p1;
        }
    }
    __syncthreads();
    if (tid < MT) {
        int n = n0 + tid;
        if (n < NWIN)
            g_scores[b * NWPAD + n] = sPart[0][tid] + sPart[1][tid];
    }
}

// ---------------------------------------------------------------------------
// Partial weighted sum: grid (NH/128, NB, NSEG), 128 thr. Softmax recomputed
// per CTA (scores L2-hot), segment of 504 windows gathered with high MLP.
__global__ void __launch_bounds__(128) k_out_part() {
    int b = blockIdx.y;
    int seg = blockIdx.z;
    int h = blockIdx.x * 128 + threadIdx.x;
    int tid = threadIdx.x;
    __shared__ float sattn[WSEG];
    __shared__ int   swn[WSEG];
    __shared__ float red[128];

    // global softmax stats
    float mx = -1e30f;
    for (int n = tid; n < NWIN; n += 128)
        mx = fmaxf(mx, g_scores[b * NWPAD + n]);
    red[tid] = mx;
    __syncthreads();
    for (int s = 64; s > 0; s >>= 1) {
        if (tid < s) red[tid] = fmaxf(red[tid], red[tid + s]);
        __syncthreads();
    }
    mx = red[0];
    __syncthreads();
    float sum = 0.f;
    int j0 = seg * WSEG;
    for (int n = tid; n < NWIN; n += 128) {
        float e = __expf(g_scores[b * NWPAD + n] - mx);
        sum += e;
        int r = n - j0;
        if (r >= 0 && r < WSEG) { sattn[r] = e; swn[r] = g_win[n]; }
    }
    red[tid] = sum;
    __syncthreads();
    for (int s = 64; s > 0; s >>= 1) {
        if (tid < s) red[tid] += red[tid + s];
        __syncthreads();
    }
    float inv = 1.f / red[0];
    __syncthreads();

    const float* tb = g_table + h;
    float a0 = 0.f, a1 = 0.f;
#pragma unroll 8
    for (int j = 0; j < WSEG; j += 2) {
        int w0 = swn[j], w1 = swn[j + 1];
        const float* p0 = tb + (size_t)(((w0 >> 16) - 1) * NB + b) * NS * NH;
        const float* p1 = tb + (size_t)(((w1 >> 16) - 1) * NB + b) * NS * NH;
        a0 += sattn[j]     * fmaxf(p0[(w0 & 255) * NH], p0[((w0 >> 8) & 255) * NH]);
        a1 += sattn[j + 1] * fmaxf(p1[(w1 & 255) * NH], p1[((w1 >> 8) & 255) * NH]);
    }
    g_partial[(seg * NB + b) * NH + h] = (a0 + a1) * inv;
}

__global__ void __launch_bounds__(256) k_out_reduce(float* __restrict__ out) {
    int i = blockIdx.x * 256 + threadIdx.x;   // over NB*NH
    if (i >= NB * NH) return;
    float v = g_partial[i] + g_partial[NB * NH + i]
            + g_partial[2 * NB * NH + i] + g_partial[3 * NB * NH + i];
    out[i] = v;
}

// ---------------------------------------------------------------------------
extern "C" void kernel_launch(void* const* d_in, const int* in_sizes, int n_in,
                              void* d_out, int out_size) {
    const float* lstm = (const float*)d_in[0];
    const float* W1   = (const float*)d_in[1];
    const float* b1   = (const float*)d_in[2];
    const float* W2   = (const float*)d_in[3];
    float* out = (float*)d_out;

    k_prep<<<dim3(8, NB + 2), 256>>>(lstm, W1);
    k_scores_mma<<<dim3(NWPAD / MT, NB), 256>>>(b1, W2);
    k_out_part<<<dim3(NH / 128, NB, NSEG), 128>>>();
    k_out_reduce<<<(NB * NH + 255) / 256, 256>>>(out);
}

// round 8
// speedup vs baseline: 1.6843x; 1.1171x over previous
#include <cuda_runtime.h>
#include <cuda_fp16.h>
#include <cstdint>
#include <math.h>

#define NB 32
#define NS 64
#define NH 512
#define NA 128
#define NWIN 2016
#define NWPAD 2048
#define NLEV 7          // levels 1..6 stored (level 0 unused: width>=2)
#define MT 128
#define KT 32
#define NKT (NH / KT)
#define LDS_A 40        // padded row stride (fp16) -> 80B
#define NSEG 8
#define WSEG (NWIN / NSEG)   // 252

// Scratch (static device globals — no allocation).
__device__ float g_table[(NLEV - 1) * NB * NS * NH];   // levels 1..6, 25.2 MB
__device__ float g_scores[NB * NWPAD];
__device__ float g_partial[NSEG * NB * NH];
__device__ int   g_win[NWPAD];                   // packed: s | e2<<8 | k<<16
__device__ __half g_w1t_hi[NA * NH];             // W1^T fp16 hi (rn), [n][k]
__device__ __half g_w1t_lo[NA * NH];             // W1^T fp16 lo

// ---------------------------------------------------------------------------
__device__ __forceinline__ uint32_t smem_u32(const void* p) {
    uint32_t a;
    asm("{ .reg .u64 t; cvta.to.shared.u64 t, %1; cvt.u32.u64 %0, t; }" : "=r"(a) : "l"(p));
    return a;
}
#define LDSM_X4(r0, r1, r2, r3, a) \
    asm volatile("ldmatrix.sync.aligned.m8n8.x4.shared.b16 {%0,%1,%2,%3}, [%4];" \
        : "=r"(r0), "=r"(r1), "=r"(r2), "=r"(r3) : "r"(a))
#define CP_ASYNC16(dst, src) \
    asm volatile("cp.async.ca.shared.global [%0], [%1], 16;" :: "r"(dst), "l"(src))
#define CP_COMMIT() asm volatile("cp.async.commit_group;" ::: "memory")
#define CP_WAIT1()  asm volatile("cp.async.wait_group 1;" ::: "memory")
#define CP_WAIT0()  asm volatile("cp.async.wait_group 0;" ::: "memory")

__device__ __forceinline__ void mma_fp16(float* c, const uint32_t* a, const uint32_t* b) {
    asm volatile(
        "mma.sync.aligned.m16n8k16.row.col.f32.f16.f16.f32 "
        "{%0,%1,%2,%3}, {%4,%5,%6,%7}, {%8,%9}, {%0,%1,%2,%3};"
        : "+f"(c[0]), "+f"(c[1]), "+f"(c[2]), "+f"(c[3])
        : "r"(a[0]), "r"(a[1]), "r"(a[2]), "r"(a[3]), "r"(b[0]), "r"(b[1]));
}

__device__ __forceinline__ float4 f4max(float4 a, float4 b) {
    return make_float4(fmaxf(a.x, b.x), fmaxf(a.y, b.y), fmaxf(a.z, b.z), fmaxf(a.w, b.w));
}
__device__ __forceinline__ uint32_t packh2(float a, float b) {
    __half2 h = __floats2half2_rn(a, b);
    return *(uint32_t*)&h;
}

// ---------------------------------------------------------------------------
// Prep: grid (8, NB+2), 256 threads. Coalesced q-major float4 layout.
__global__ void __launch_bounds__(256) k_prep(const float* __restrict__ lstm,
                                              const float* __restrict__ W1) {
    int tid = threadIdx.x;
    int by = blockIdx.y, bx = blockIdx.x;

    if (by < NB) {
        int b = by, h0 = bx * 64;
        __shared__ float4 buf[2][NS][16];
        int q = tid & 15, i0 = tid >> 4;
#pragma unroll
        for (int c = 0; c < 4; c++) {
            int i = i0 + c * 16;
            buf[0][i][q] = *(const float4*)(lstm + ((size_t)(b * NS + i)) * NH + h0 + q * 4);
        }
        __syncthreads();
        int cur = 0;
        for (int k = 1; k < NLEV; k++) {
            int half = 1 << (k - 1);
            int nxt = cur ^ 1;
#pragma unroll
            for (int c = 0; c < 4; c++) {
                int i = i0 + c * 16;
                float4 v = buf[cur][i][q];
                if (i + half < NS) v = f4max(v, buf[cur][i + half][q]);
                buf[nxt][i][q] = v;
                *(float4*)(g_table + ((size_t)((k - 1) * NB + b) * NS + i) * NH + h0 + q * 4) = v;
            }
            __syncthreads();
            cur = nxt;
        }
    } else if (by == NB) {
        int n = bx * 256 + tid;
        if (n >= NWPAD) return;
        int nn = n < NWIN ? n : NWIN - 1;
        int w = 2;
#pragma unroll 1
        for (int ww = 3; ww <= NS; ww++) {
            int F = (129 - ww) * (ww - 2) / 2;
            if (F <= nn) w = ww;
        }
        int Fw = (129 - w) * (w - 2) / 2;
        int s = nn - Fw;
        int k = 31 - __clz(w);
        int e2 = s + w - (1 << k);
        g_win[n] = s | (e2 << 8) | (k << 16);
    } else {
        int t = bx * 256 + tid;
        int n = t >> 3;
        int kc = (t & 7) * 64;
        if (n >= NA) return;
#pragma unroll 4
        for (int k = kc; k < kc + 64; k++) {
            float v = W1[k * NA + n];
            __half h = __float2half_rn(v);
            g_w1t_hi[n * NH + k] = h;
            g_w1t_lo[n * NH + k] = __float2half_rn(v - __half2float(h));
        }
    }
}

// ---------------------------------------------------------------------------
// Score kernel: fp16 2-pass (A single rn-fp16, B split hi/lo).
// 256 thr, occ 2. B double-stage cp.async; s-row prefetched across MMAs.
__global__ void __launch_bounds__(256, 2) k_scores_mma(
    const float* __restrict__ b1, const float* __restrict__ W2)
{
    __shared__ __align__(16) __half aH[MT][LDS_A];
    __shared__ __align__(16) __half bHi[2][NA][LDS_A];
    __shared__ __align__(16) __half bLo[2][NA][LDS_A];
    __shared__ float sPart[2][MT];
    __shared__ float sb1[NA], sw2[NA];
    __shared__ int s_win[MT];

    int b  = blockIdx.y;
    int n0 = blockIdx.x * MT;
    int tid  = threadIdx.x;
    int wid  = tid >> 5, lane = tid & 31;
    int wm = wid & 3, wn = wid >> 2;

    if (tid < MT) {
        int n = n0 + tid;
        s_win[tid] = g_win[n < NWIN ? n : NWIN - 1];
    }
    if (tid >= MT && tid < MT + NA) { int a = tid - MT; sb1[a] = b1[a]; sw2[a] = W2[a]; }

    float acc[2][8][4];
#pragma unroll
    for (int mt = 0; mt < 2; mt++)
#pragma unroll
        for (int nt = 0; nt < 8; nt++)
#pragma unroll
            for (int j = 0; j < 4; j++) acc[mt][nt][j] = 0.f;

    int am = tid >> 1;
    int ac0 = (tid & 1) * 16;
    int bn = tid >> 1;
    int bco = (tid & 1) * 32;
    const char* w1hiP = (const char*)g_w1t_hi + (size_t)bn * (NH * 2) + bco;
    const char* w1loP = (const char*)g_w1t_lo + (size_t)bn * (NH * 2) + bco;
    uint32_t bHiD0 = smem_u32(&bHi[0][bn][0]) + bco;
    uint32_t bLoD0 = smem_u32(&bLo[0][bn][0]) + bco;
    const uint32_t stgStride = NA * LDS_A * 2;

    __syncthreads();   // s_win ready

    uint32_t aRow = (uint32_t)(lane & 15);
    uint32_t aCol = (uint32_t)(lane >> 4) * 16u;
    uint32_t bRow = (uint32_t)((lane & 7) + ((lane >> 4) << 3));
    uint32_t bCol = (uint32_t)((lane >> 3) & 1) * 16u;
    uint32_t aBase = smem_u32(&aH[0][0]);
    uint32_t bHiBase = smem_u32(&bHi[0][0][0]), bLoBase = smem_u32(&bLo[0][0][0]);

    int wi = s_win[am];
    int ws = wi & 255, we2 = (wi >> 8) & 255, wk = wi >> 16;
    const float* gbase = g_table + ((size_t)((wk - 1) * NB + b) * NS) * NH + ac0;
    const float* sRowBase  = gbase + (size_t)ws * NH;
    const float* e2RowBase = gbase + (size_t)we2 * NH;

    // prologue
    CP_ASYNC16(bHiD0,      w1hiP);
    CP_ASYNC16(bHiD0 + 16, w1hiP + 16);
    CP_ASYNC16(bLoD0,      w1loP);
    CP_ASYNC16(bLoD0 + 16, w1loP + 16);
    CP_COMMIT();
    float4 rs0 = *(const float4*)(sRowBase);
    float4 rs1 = *(const float4*)(sRowBase + 4);
    float4 rs2 = *(const float4*)(sRowBase + 8);
    float4 rs3 = *(const float4*)(sRowBase + 12);

    for (int t = 0; t < NKT; t++) {
        int cur = t & 1, nxt = cur ^ 1;
        bool more = (t + 1 < NKT);
        int th0 = t * KT;

        // A fill: prefetched s-row + fresh e2-row, rn-fp16 pack
        {
            const float* pe = e2RowBase + th0;
            float4 v0 = f4max(rs0, *(const float4*)(pe));
            float4 v1 = f4max(rs1, *(const float4*)(pe + 4));
            float4 v2 = f4max(rs2, *(const float4*)(pe + 8));
            float4 v3 = f4max(rs3, *(const float4*)(pe + 12));
            uint4 r0, r1;
            r0.x = packh2(v0.x, v0.y); r0.y = packh2(v0.z, v0.w);
            r0.z = packh2(v1.x, v1.y); r0.w = packh2(v1.z, v1.w);
            r1.x = packh2(v2.x, v2.y); r1.y = packh2(v2.z, v2.w);
            r1.z = packh2(v3.x, v3.y); r1.w = packh2(v3.z, v3.w);
            *(uint4*)&aH[am][ac0]     = r0;
            *(uint4*)&aH[am][ac0 + 8] = r1;
        }
        if (more) {
            const char* hp = w1hiP + (t + 1) * (KT * 2);
            const char* lp = w1loP + (t + 1) * (KT * 2);
            uint32_t hd = bHiD0 + (uint32_t)nxt * stgStride;
            uint32_t ld = bLoD0 + (uint32_t)nxt * stgStride;
            CP_ASYNC16(hd,      hp);
            CP_ASYNC16(hd + 16, hp + 16);
            CP_ASYNC16(ld,      lp);
            CP_ASYNC16(ld + 16, lp + 16);
            CP_COMMIT();
            CP_WAIT1();
        } else {
            CP_WAIT0();
        }
        __syncthreads();

        if (more) {
            const float* ps = sRowBase + (t + 1) * KT;
            rs0 = *(const float4*)(ps);
            rs1 = *(const float4*)(ps + 4);
            rs2 = *(const float4*)(ps + 8);
            rs3 = *(const float4*)(ps + 12);
        }

        uint32_t bHiB = bHiBase + (uint32_t)cur * stgStride;
        uint32_t bLoB = bLoBase + (uint32_t)cur * stgStride;
#pragma unroll
        for (int ks = 0; ks < 2; ks++) {
            uint32_t kOff = (uint32_t)ks * 32u;
            uint32_t A[2][4];
#pragma unroll
            for (int mt = 0; mt < 2; mt++) {
                uint32_t row = (uint32_t)(wm * 32 + mt * 16) + aRow;
                uint32_t off = row * (LDS_A * 2) + kOff + aCol;
                LDSM_X4(A[mt][0], A[mt][1], A[mt][2], A[mt][3], aBase + off);
            }
#pragma unroll
            for (int np = 0; np < 4; np++) {
                uint32_t nrow = (uint32_t)(wn * 64 + np * 16) + bRow;
                uint32_t off = nrow * (LDS_A * 2) + kOff + bCol;
                uint32_t Bh[4], Bl[4];
                LDSM_X4(Bh[0], Bh[1], Bh[2], Bh[3], bHiB + off);
                LDSM_X4(Bl[0], Bl[1], Bl[2], Bl[3], bLoB + off);
#pragma unroll
                for (int mt = 0; mt < 2; mt++) {
#pragma unroll
                    for (int h = 0; h < 2; h++) {
                        int nt = np * 2 + h;
                        mma_fp16(acc[mt][nt], A[mt], &Bh[h * 2]);
                        mma_fp16(acc[mt][nt], A[mt], &Bl[h * 2]);
                    }
                }
            }
        }
        __syncthreads();
    }

    // epilogue: relu(acc + b1) dot W2, reduce over n
    int gq = lane >> 2;
    int gr = lane & 3;
#pragma unroll
    for (int mt = 0; mt < 2; mt++) {
        float p0 = 0.f, p1 = 0.f;
#pragma unroll
        for (int nt = 0; nt < 8; nt++) {
            int col = wn * 64 + nt * 8 + gr * 2;
            float b1a = sb1[col], b1b = sb1[col + 1];
            float w2a = sw2[col], w2b = sw2[col + 1];
            p0 = fmaf(fmaxf(acc[mt][nt][0] + b1a, 0.f), w2a, p0);
            p0 = fmaf(fmaxf(acc[mt][nt][1] + b1b, 0.f), w2b, p0);
            p1 = fmaf(fmaxf(acc[mt][nt][2] + b1a, 0.f), w2a, p1);
            p1 = fmaf(fmaxf(acc[mt][nt][3] + b1b, 0.f), w2b, p1);
        }
#pragma unroll
        for (int off = 1; off <= 2; off <<= 1) {
            p0 += __shfl_xor_sync(0xffffffffu, p0, off);
            p1 += __shfl_xor_sync(0xffffffffu, p1, off);
        }
        if (gr == 0) {
            int row = wm * 32 + mt * 16 + gq;
            sPart[wn][row]     = p0;
            sPart[wn][row + 8] = p1;
        }
    }
    __syncthreads();
    if (tid < MT) {
        int n = n0 + tid;
        if (n < NWIN)
            g_scores[b * NWPAD + n] = sPart[0][tid] + sPart[1][tid];
    }
}

// ---------------------------------------------------------------------------
// Partial weighted sum: grid (NH/128, NB, NSEG), 128 thr.
__global__ void __launch_bounds__(128) k_out_part() {
    int b = blockIdx.y;
    int seg = blockIdx.z;
    int h = blockIdx.x * 128 + threadIdx.x;
    int tid = threadIdx.x;
    __shared__ float sattn[WSEG];
    __shared__ int   swn[WSEG];
    __shared__ float red[128];

    float mx = -1e30f;
    for (int n = tid; n < NWIN; n += 128)
        mx = fmaxf(mx, g_scores[b * NWPAD + n]);
    red[tid] = mx;
    __syncthreads();
    for (int s = 64; s > 0; s >>= 1) {
        if (tid < s) red[tid] = fmaxf(red[tid], red[tid + s]);
        __syncthreads();
    }
    mx = red[0];
    __syncthreads();
    float sum = 0.f;
    int j0 = seg * WSEG;
    for (int n = tid; n < NWIN; n += 128) {
        float e = __expf(g_scores[b * NWPAD + n] - mx);
        sum += e;
        int r = n - j0;
        if (r >= 0 && r < WSEG) { sattn[r] = e; swn[r] = g_win[n]; }
    }
    red[tid] = sum;
    __syncthreads();
    for (int s = 64; s > 0; s >>= 1) {
        if (tid < s) red[tid] += red[tid + s];
        __syncthreads();
    }
    float inv = 1.f / red[0];
    __syncthreads();

    const float* tb = g_table + h;
    float a0 = 0.f, a1 = 0.f;
#pragma unroll 6
    for (int j = 0; j < WSEG; j += 2) {
        int w0 = swn[j], w1 = swn[j + 1];
        const float* p0 = tb + (size_t)(((w0 >> 16) - 1) * NB + b) * NS * NH;
        const float* p1 = tb + (size_t)(((w1 >> 16) - 1) * NB + b) * NS * NH;
        a0 += sattn[j]     * fmaxf(p0[(w0 & 255) * NH], p0[((w0 >> 8) & 255) * NH]);
        a1 += sattn[j + 1] * fmaxf(p1[(w1 & 255) * NH], p1[((w1 >> 8) & 255) * NH]);
    }
    g_partial[(seg * NB + b) * NH + h] = (a0 + a1) * inv;
}

__global__ void __launch_bounds__(256) k_out_reduce(float* __restrict__ out) {
    int i = blockIdx.x * 256 + threadIdx.x;   // over NB*NH
    if (i >= NB * NH) return;
    float v = 0.f;
#pragma unroll
    for (int s = 0; s < NSEG; s++) v += g_partial[s * NB * NH + i];
    out[i] = v;
}

// ---------------------------------------------------------------------------
extern "C" void kernel_launch(void* const* d_in, const int* in_sizes, int n_in,
                              void* d_out, int out_size) {
    const float* lstm = (const float*)d_in[0];
    const float* W1   = (const float*)d_in[1];
    const float* b1   = (const float*)d_in[2];
    const float* W2   = (const float*)d_in[3];
    float* out = (float*)d_out;

    k_prep<<<dim3(8, NB + 2), 256>>>(lstm, W1);
    k_scores_mma<<<dim3(NWPAD / MT, NB), 256>>>(b1, W2);
    k_out_part<<<dim3(NH / 128, NB, NSEG), 128>>>();
    k_out_reduce<<<(NB * NH + 255) / 256, 256>>>(out);
}

// round 9
// speedup vs baseline: 2.2458x; 1.3333x over previous
#include <cuda_runtime.h>
#include <cuda_fp16.h>
#include <cstdint>
#include <math.h>

#define NB 32
#define NS 64
#define NH 512
#define NA 128
#define NWIN 2016
#define NWPAD 2048
#define NLEV 7          // levels 1..6 stored (level 0 unused: width>=2)
#define MT 128
#define KT 32
#define NKT (NH / KT)
#define LDS_A 40        // padded row stride (fp16) -> 80B
#define NSEG 8
#define WSEG (NWIN / NSEG)   // 252

// Scratch (static device globals — no allocation).
__device__ float g_table[(NLEV - 1) * NB * NS * NH];   // levels 1..6, 25.2 MB
__device__ float g_scores[NB * NWPAD];
__device__ float g_partial[NSEG * NB * NH];
__device__ int   g_win[NWPAD];                   // packed: s | e2<<8 | k<<16
__device__ __half g_w1t[NA * NH];                // W1^T fp16 (rn), [n][k]

// ---------------------------------------------------------------------------
__device__ __forceinline__ uint32_t smem_u32(const void* p) {
    uint32_t a;
    asm("{ .reg .u64 t; cvta.to.shared.u64 t, %1; cvt.u32.u64 %0, t; }" : "=r"(a) : "l"(p));
    return a;
}
#define LDSM_X4(r0, r1, r2, r3, a) \
    asm volatile("ldmatrix.sync.aligned.m8n8.x4.shared.b16 {%0,%1,%2,%3}, [%4];" \
        : "=r"(r0), "=r"(r1), "=r"(r2), "=r"(r3) : "r"(a))
#define CP_ASYNC16(dst, src) \
    asm volatile("cp.async.ca.shared.global [%0], [%1], 16;" :: "r"(dst), "l"(src))
#define CP_COMMIT() asm volatile("cp.async.commit_group;" ::: "memory")
#define CP_WAIT1()  asm volatile("cp.async.wait_group 1;" ::: "memory")
#define CP_WAIT0()  asm volatile("cp.async.wait_group 0;" ::: "memory")

__device__ __forceinline__ void mma_fp16(float* c, const uint32_t* a, const uint32_t* b) {
    asm volatile(
        "mma.sync.aligned.m16n8k16.row.col.f32.f16.f16.f32 "
        "{%0,%1,%2,%3}, {%4,%5,%6,%7}, {%8,%9}, {%0,%1,%2,%3};"
        : "+f"(c[0]), "+f"(c[1]), "+f"(c[2]), "+f"(c[3])
        : "r"(a[0]), "r"(a[1]), "r"(a[2]), "r"(a[3]), "r"(b[0]), "r"(b[1]));
}

__device__ __forceinline__ float4 f4max(float4 a, float4 b) {
    return make_float4(fmaxf(a.x, b.x), fmaxf(a.y, b.y), fmaxf(a.z, b.z), fmaxf(a.w, b.w));
}
__device__ __forceinline__ uint32_t packh2(float a, float b) {
    __half2 h = __floats2half2_rn(a, b);
    return *(uint32_t*)&h;
}

// ---------------------------------------------------------------------------
// Prep: grid (8, NB+2), 256 threads. Coalesced q-major float4 layout.
__global__ void __launch_bounds__(256) k_prep(const float* __restrict__ lstm,
                                              const float* __restrict__ W1) {
    int tid = threadIdx.x;
    int by = blockIdx.y, bx = blockIdx.x;

    if (by < NB) {
        int b = by, h0 = bx * 64;
        __shared__ float4 buf[2][NS][16];
        int q = tid & 15, i0 = tid >> 4;
#pragma unroll
        for (int c = 0; c < 4; c++) {
            int i = i0 + c * 16;
            buf[0][i][q] = *(const float4*)(lstm + ((size_t)(b * NS + i)) * NH + h0 + q * 4);
        }
        __syncthreads();
        int cur = 0;
        for (int k = 1; k < NLEV; k++) {
            int half = 1 << (k - 1);
            int nxt = cur ^ 1;
#pragma unroll
            for (int c = 0; c < 4; c++) {
                int i = i0 + c * 16;
                float4 v = buf[cur][i][q];
                if (i + half < NS) v = f4max(v, buf[cur][i + half][q]);
                buf[nxt][i][q] = v;
                *(float4*)(g_table + ((size_t)((k - 1) * NB + b) * NS + i) * NH + h0 + q * 4) = v;
            }
            __syncthreads();
            cur = nxt;
        }
    } else if (by == NB) {
        int n = bx * 256 + tid;
        if (n >= NWPAD) return;
        int nn = n < NWIN ? n : NWIN - 1;
        int w = 2;
#pragma unroll 1
        for (int ww = 3; ww <= NS; ww++) {
            int F = (129 - ww) * (ww - 2) / 2;
            if (F <= nn) w = ww;
        }
        int Fw = (129 - w) * (w - 2) / 2;
        int s = nn - Fw;
        int k = 31 - __clz(w);
        int e2 = s + w - (1 << k);
        g_win[n] = s | (e2 << 8) | (k << 16);
    } else {
        int t = bx * 256 + tid;
        int n = t >> 3;
        int kc = (t & 7) * 64;
        if (n >= NA) return;
#pragma unroll 4
        for (int k = kc; k < kc + 64; k++)
            g_w1t[n * NH + k] = __float2half_rn(W1[k * NA + n]);
    }
}

// ---------------------------------------------------------------------------
// Score kernel: single-pass fp16 HMMA. 256 thr, occ 2.
// B double-stage cp.async; s-row prefetched across MMAs.
__global__ void __launch_bounds__(256, 2) k_scores_mma(
    const float* __restrict__ b1, const float* __restrict__ W2)
{
    __shared__ __align__(16) __half aH[MT][LDS_A];
    __shared__ __align__(16) __half bH[2][NA][LDS_A];
    __shared__ float sPart[2][MT];
    __shared__ float sb1[NA], sw2[NA];
    __shared__ int s_win[MT];

    int b  = blockIdx.y;
    int n0 = blockIdx.x * MT;
    int tid  = threadIdx.x;
    int wid  = tid >> 5, lane = tid & 31;
    int wm = wid & 3, wn = wid >> 2;

    if (tid < MT) {
        int n = n0 + tid;
        s_win[tid] = g_win[n < NWIN ? n : NWIN - 1];
    }
    if (tid >= MT && tid < MT + NA) { int a = tid - MT; sb1[a] = b1[a]; sw2[a] = W2[a]; }

    float acc[2][8][4];
#pragma unroll
    for (int mt = 0; mt < 2; mt++)
#pragma unroll
        for (int nt = 0; nt < 8; nt++)
#pragma unroll
            for (int j = 0; j < 4; j++) acc[mt][nt][j] = 0.f;

    int am = tid >> 1;
    int ac0 = (tid & 1) * 16;
    int bn = tid >> 1;
    int bco = (tid & 1) * 32;
    const char* w1P = (const char*)g_w1t + (size_t)bn * (NH * 2) + bco;
    uint32_t bD0 = smem_u32(&bH[0][bn][0]) + bco;
    const uint32_t stgStride = NA * LDS_A * 2;

    __syncthreads();   // s_win ready

    uint32_t aRow = (uint32_t)(lane & 15);
    uint32_t aCol = (uint32_t)(lane >> 4) * 16u;
    uint32_t bRow = (uint32_t)((lane & 7) + ((lane >> 4) << 3));
    uint32_t bCol = (uint32_t)((lane >> 3) & 1) * 16u;
    uint32_t aBase = smem_u32(&aH[0][0]);
    uint32_t bBase = smem_u32(&bH[0][0][0]);

    int wi = s_win[am];
    int ws = wi & 255, we2 = (wi >> 8) & 255, wk = wi >> 16;
    const float* gbase = g_table + ((size_t)((wk - 1) * NB + b) * NS) * NH + ac0;
    const float* sRowBase  = gbase + (size_t)ws * NH;
    const float* e2RowBase = gbase + (size_t)we2 * NH;

    // prologue
    CP_ASYNC16(bD0,      w1P);
    CP_ASYNC16(bD0 + 16, w1P + 16);
    CP_COMMIT();
    float4 rs0 = *(const float4*)(sRowBase);
    float4 rs1 = *(const float4*)(sRowBase + 4);
    float4 rs2 = *(const float4*)(sRowBase + 8);
    float4 rs3 = *(const float4*)(sRowBase + 12);

    for (int t = 0; t < NKT; t++) {
        int cur = t & 1, nxt = cur ^ 1;
        bool more = (t + 1 < NKT);
        int th0 = t * KT;

        // A fill: prefetched s-row + fresh e2-row, rn-fp16 pack
        {
            const float* pe = e2RowBase + th0;
            float4 v0 = f4max(rs0, *(const float4*)(pe));
            float4 v1 = f4max(rs1, *(const float4*)(pe + 4));
            float4 v2 = f4max(rs2, *(const float4*)(pe + 8));
            float4 v3 = f4max(rs3, *(const float4*)(pe + 12));
            uint4 r0, r1;
            r0.x = packh2(v0.x, v0.y); r0.y = packh2(v0.z, v0.w);
            r0.z = packh2(v1.x, v1.y); r0.w = packh2(v1.z, v1.w);
            r1.x = packh2(v2.x, v2.y); r1.y = packh2(v2.z, v2.w);
            r1.z = packh2(v3.x, v3.y); r1.w = packh2(v3.z, v3.w);
            *(uint4*)&aH[am][ac0]     = r0;
            *(uint4*)&aH[am][ac0 + 8] = r1;
        }
        if (more) {
            const char* hp = w1P + (t + 1) * (KT * 2);
            uint32_t hd = bD0 + (uint32_t)nxt * stgStride;
            CP_ASYNC16(hd,      hp);
            CP_ASYNC16(hd + 16, hp + 16);
            CP_COMMIT();
            CP_WAIT1();
        } else {
            CP_WAIT0();
        }
        __syncthreads();

        if (more) {
            const float* ps = sRowBase + (t + 1) * KT;
            rs0 = *(const float4*)(ps);
            rs1 = *(const float4*)(ps + 4);
            rs2 = *(const float4*)(ps + 8);
            rs3 = *(const float4*)(ps + 12);
        }

        uint32_t bB = bBase + (uint32_t)cur * stgStride;
#pragma unroll
        for (int ks = 0; ks < 2; ks++) {
            uint32_t kOff = (uint32_t)ks * 32u;
            uint32_t A[2][4];
#pragma unroll
            for (int mt = 0; mt < 2; mt++) {
                uint32_t row = (uint32_t)(wm * 32 + mt * 16) + aRow;
                uint32_t off = row * (LDS_A * 2) + kOff + aCol;
                LDSM_X4(A[mt][0], A[mt][1], A[mt][2], A[mt][3], aBase + off);
            }
#pragma unroll
            for (int np = 0; np < 4; np++) {
                uint32_t nrow = (uint32_t)(wn * 64 + np * 16) + bRow;
                uint32_t off = nrow * (LDS_A * 2) + kOff + bCol;
                uint32_t B[4];
                LDSM_X4(B[0], B[1], B[2], B[3], bB + off);
#pragma unroll
                for (int mt = 0; mt < 2; mt++) {
#pragma unroll
                    for (int h = 0; h < 2; h++) {
                        mma_fp16(acc[mt][np * 2 + h], A[mt], &B[h * 2]);
                    }
                }
            }
        }
        __syncthreads();
    }

    // epilogue: relu(acc + b1) dot W2, reduce over n
    int gq = lane >> 2;
    int gr = lane & 3;
#pragma unroll
    for (int mt = 0; mt < 2; mt++) {
        float p0 = 0.f, p1 = 0.f;
#pragma unroll
        for (int nt = 0; nt < 8; nt++) {
            int col = wn * 64 + nt * 8 + gr * 2;
            float b1a = sb1[col], b1b = sb1[col + 1];
            float w2a = sw2[col], w2b = sw2[col + 1];
            p0 = fmaf(fmaxf(acc[mt][nt][0] + b1a, 0.f), w2a, p0);
            p0 = fmaf(fmaxf(acc[mt][nt][1] + b1b, 0.f), w2b, p0);
            p1 = fmaf(fmaxf(acc[mt][nt][2] + b1a, 0.f), w2a, p1);
            p1 = fmaf(fmaxf(acc[mt][nt][3] + b1b, 0.f), w2b, p1);
        }
#pragma unroll
        for (int off = 1; off <= 2; off <<= 1) {
            p0 += __shfl_xor_sync(0xffffffffu, p0, off);
            p1 += __shfl_xor_sync(0xffffffffu, p1, off);
        }
        if (gr == 0) {
            int row = wm * 32 + mt * 16 + gq;
            sPart[wn][row]     = p0;
            sPart[wn][row + 8] = p1;
        }
    }
    __syncthreads();
    if (tid < MT) {
        int n = n0 + tid;
        if (n < NWIN)
            g_scores[b * NWPAD + n] = sPart[0][tid] + sPart[1][tid];
    }
}

// ---------------------------------------------------------------------------
// Partial weighted sum: grid (NH/128, NB, NSEG), 128 thr.
__global__ void __launch_bounds__(128) k_out_part() {
    int b = blockIdx.y;
    int seg = blockIdx.z;
    int h = blockIdx.x * 128 + threadIdx.x;
    int tid = threadIdx.x;
    __shared__ float sattn[WSEG];
    __shared__ int   swn[WSEG];
    __shared__ float red[128];

    float mx = -1e30f;
    for (int n = tid; n < NWIN; n += 128)
        mx = fmaxf(mx, g_scores[b * NWPAD + n]);
    red[tid] = mx;
    __syncthreads();
    for (int s = 64; s > 0; s >>= 1) {
        if (tid < s) red[tid] = fmaxf(red[tid], red[tid + s]);
        __syncthreads();
    }
    mx = red[0];
    __syncthreads();
    float sum = 0.f;
    int j0 = seg * WSEG;
    for (int n = tid; n < NWIN; n += 128) {
        float e = __expf(g_scores[b * NWPAD + n] - mx);
        sum += e;
        int r = n - j0;
        if (r >= 0 && r < WSEG) { sattn[r] = e; swn[r] = g_win[n]; }
    }
    red[tid] = sum;
    __syncthreads();
    for (int s = 64; s > 0; s >>= 1) {
        if (tid < s) red[tid] += red[tid + s];
        __syncthreads();
    }
    float inv = 1.f / red[0];
    __syncthreads();

    const float* tb = g_table + h;
    float a0 = 0.f, a1 = 0.f;
#pragma unroll 6
    for (int j = 0; j < WSEG; j += 2) {
        int w0 = swn[j], w1 = swn[j + 1];
        const float* p0 = tb + (size_t)(((w0 >> 16) - 1) * NB + b) * NS * NH;
        const float* p1 = tb + (size_t)(((w1 >> 16) - 1) * NB + b) * NS * NH;
        a0 += sattn[j]     * fmaxf(p0[(w0 & 255) * NH], p0[((w0 >> 8) & 255) * NH]);
        a1 += sattn[j + 1] * fmaxf(p1[(w1 & 255) * NH], p1[((w1 >> 8) & 255) * NH]);
    }
    g_partial[(seg * NB + b) * NH + h] = (a0 + a1) * inv;
}

__global__ void __launch_bounds__(256) k_out_reduce(float* __restrict__ out) {
    int i = blockIdx.x * 256 + threadIdx.x;   // over NB*NH
    if (i >= NB * NH) return;
    float v = 0.f;
#pragma unroll
    for (int s = 0; s < NSEG; s++) v += g_partial[s * NB * NH + i];
    out[i] = v;
}

// ---------------------------------------------------------------------------
extern "C" void kernel_launch(void* const* d_in, const int* in_sizes, int n_in,
                              void* d_out, int out_size) {
    const float* lstm = (const float*)d_in[0];
    const float* W1   = (const float*)d_in[1];
    const float* b1   = (const float*)d_in[2];
    const float* W2   = (const float*)d_in[3];
    float* out = (float*)d_out;

    k_prep<<<dim3(8, NB + 2), 256>>>(lstm, W1);
    k_scores_mma<<<dim3(NWPAD / MT, NB), 256>>>(b1, W2);
    k_out_part<<<dim3(NH / 128, NB, NSEG), 128>>>();
    k_out_reduce<<<(NB * NH + 255) / 256, 256>>>(out);
}

// round 10
// speedup vs baseline: 2.5971x; 1.1565x over previous
#include <cuda_runtime.h>
#include <cuda_fp16.h>
#include <cstdint>
#include <math.h>

#define NB 32
#define NS 64
#define NH 512
#define NA 128
#define NWIN 2016
#define NWPAD 2048
#define NLEV 7          // levels 1..6 stored (level 0 unused: width>=2)
#define MT 128
#define KT 32
#define NKT (NH / KT)
#define LDS_A 40        // padded row stride (fp16) -> 80B
#define NSEG 8
#define WSEG (NWIN / NSEG)   // 252

// Scratch (static device globals — no allocation).
__device__ __half g_tab16[(NLEV - 1) * NB * NS * NH];  // fp16 max-table, 12.6 MB
__device__ float g_scores[NB * NWPAD];
__device__ float g_partial[NSEG * NB * NH];
__device__ int   g_win[NWPAD];                   // packed: s | e2<<8 | k<<16
__device__ __half g_w1t[NA * NH];                // W1^T fp16 (rn), [n][k]

// ---------------------------------------------------------------------------
__device__ __forceinline__ uint32_t smem_u32(const void* p) {
    uint32_t a;
    asm("{ .reg .u64 t; cvta.to.shared.u64 t, %1; cvt.u32.u64 %0, t; }" : "=r"(a) : "l"(p));
    return a;
}
#define LDSM_X4(r0, r1, r2, r3, a) \
    asm volatile("ldmatrix.sync.aligned.m8n8.x4.shared.b16 {%0,%1,%2,%3}, [%4];" \
        : "=r"(r0), "=r"(r1), "=r"(r2), "=r"(r3) : "r"(a))
#define CP_ASYNC16(dst, src) \
    asm volatile("cp.async.ca.shared.global [%0], [%1], 16;" :: "r"(dst), "l"(src))
#define CP_COMMIT() asm volatile("cp.async.commit_group;" ::: "memory")
#define CP_WAIT1()  asm volatile("cp.async.wait_group 1;" ::: "memory")
#define CP_WAIT0()  asm volatile("cp.async.wait_group 0;" ::: "memory")

__device__ __forceinline__ void mma_fp16(float* c, const uint32_t* a, const uint32_t* b) {
    asm volatile(
        "mma.sync.aligned.m16n8k16.row.col.f32.f16.f16.f32 "
        "{%0,%1,%2,%3}, {%4,%5,%6,%7}, {%8,%9}, {%0,%1,%2,%3};"
        : "+f"(c[0]), "+f"(c[1]), "+f"(c[2]), "+f"(c[3])
        : "r"(a[0]), "r"(a[1]), "r"(a[2]), "r"(a[3]), "r"(b[0]), "r"(b[1]));
}

__device__ __forceinline__ float4 f4max(float4 a, float4 b) {
    return make_float4(fmaxf(a.x, b.x), fmaxf(a.y, b.y), fmaxf(a.z, b.z), fmaxf(a.w, b.w));
}
__device__ __forceinline__ uint32_t packh2(float a, float b) {
    __half2 h = __floats2half2_rn(a, b);
    return *(uint32_t*)&h;
}
__device__ __forceinline__ uint32_t hmax2u(uint32_t a, uint32_t b) {
    __half2 r = __hmax2(*(__half2*)&a, *(__half2*)&b);
    return *(uint32_t*)&r;
}

// ---------------------------------------------------------------------------
// Prep: grid (8, NB+2), 256 threads. fp32 levels in smem, fp16 stores.
__global__ void __launch_bounds__(256) k_prep(const float* __restrict__ lstm,
                                              const float* __restrict__ W1) {
    int tid = threadIdx.x;
    int by = blockIdx.y, bx = blockIdx.x;

    if (by < NB) {
        int b = by, h0 = bx * 64;
        __shared__ float4 buf[2][NS][16];
        int q = tid & 15, i0 = tid >> 4;
#pragma unroll
        for (int c = 0; c < 4; c++) {
            int i = i0 + c * 16;
            buf[0][i][q] = *(const float4*)(lstm + ((size_t)(b * NS + i)) * NH + h0 + q * 4);
        }
        __syncthreads();
        int cur = 0;
        for (int k = 1; k < NLEV; k++) {
            int half = 1 << (k - 1);
            int nxt = cur ^ 1;
#pragma unroll
            for (int c = 0; c < 4; c++) {
                int i = i0 + c * 16;
                float4 v = buf[cur][i][q];
                if (i + half < NS) v = f4max(v, buf[cur][i + half][q]);
                buf[nxt][i][q] = v;
                uint2 hv;
                hv.x = packh2(v.x, v.y);
                hv.y = packh2(v.z, v.w);
                *(uint2*)(g_tab16 + ((size_t)((k - 1) * NB + b) * NS + i) * NH + h0 + q * 4) = hv;
            }
            __syncthreads();
            cur = nxt;
        }
    } else if (by == NB) {
        int n = bx * 256 + tid;
        if (n >= NWPAD) return;
        int nn = n < NWIN ? n : NWIN - 1;
        int w = 2;
#pragma unroll 1
        for (int ww = 3; ww <= NS; ww++) {
            int F = (129 - ww) * (ww - 2) / 2;
            if (F <= nn) w = ww;
        }
        int Fw = (129 - w) * (w - 2) / 2;
        int s = nn - Fw;
        int k = 31 - __clz(w);
        int e2 = s + w - (1 << k);
        g_win[n] = s | (e2 << 8) | (k << 16);
    } else {
        int t = bx * 256 + tid;
        int n = t >> 3;
        int kc = (t & 7) * 64;
        if (n >= NA) return;
#pragma unroll 4
        for (int k = kc; k < kc + 64; k++)
            g_w1t[n * NH + k] = __float2half_rn(W1[k * NA + n]);
    }
}

// ---------------------------------------------------------------------------
// Score kernel: single-pass fp16 HMMA, fp16-table gathers (HMAX2 merge).
__global__ void __launch_bounds__(256, 2) k_scores_mma(
    const float* __restrict__ b1, const float* __restrict__ W2)
{
    __shared__ __align__(16) __half aH[MT][LDS_A];
    __shared__ __align__(16) __half bH[2][NA][LDS_A];
    __shared__ float sPart[2][MT];
    __shared__ float sb1[NA], sw2[NA];
    __shared__ int s_win[MT];

    int b  = blockIdx.y;
    int n0 = blockIdx.x * MT;
    int tid  = threadIdx.x;
    int wid  = tid >> 5, lane = tid & 31;
    int wm = wid & 3, wn = wid >> 2;

    if (tid < MT) {
        int n = n0 + tid;
        s_win[tid] = g_win[n < NWIN ? n : NWIN - 1];
    }
    if (tid >= MT && tid < MT + NA) { int a = tid - MT; sb1[a] = b1[a]; sw2[a] = W2[a]; }

    float acc[2][8][4];
#pragma unroll
    for (int mt = 0; mt < 2; mt++)
#pragma unroll
        for (int nt = 0; nt < 8; nt++)
#pragma unroll
            for (int j = 0; j < 4; j++) acc[mt][nt][j] = 0.f;

    int am = tid >> 1;
    int ac0 = (tid & 1) * 16;            // half index within row
    int bn = tid >> 1;
    int bco = (tid & 1) * 32;
    const char* w1P = (const char*)g_w1t + (size_t)bn * (NH * 2) + bco;
    uint32_t bD0 = smem_u32(&bH[0][bn][0]) + bco;
    const uint32_t stgStride = NA * LDS_A * 2;

    __syncthreads();   // s_win ready

    uint32_t aRow = (uint32_t)(lane & 15);
    uint32_t aCol = (uint32_t)(lane >> 4) * 16u;
    uint32_t bRow = (uint32_t)((lane & 7) + ((lane >> 4) << 3));
    uint32_t bCol = (uint32_t)((lane >> 3) & 1) * 16u;
    uint32_t aBase = smem_u32(&aH[0][0]);
    uint32_t bBase = smem_u32(&bH[0][0][0]);

    int wi = s_win[am];
    int ws = wi & 255, we2 = (wi >> 8) & 255, wk = wi >> 16;
    const __half* gbase = g_tab16 + ((size_t)((wk - 1) * NB + b) * NS) * NH + ac0;
    const __half* sRowBase  = gbase + (size_t)ws * NH;
    const __half* e2RowBase = gbase + (size_t)we2 * NH;

    // prologue
    CP_ASYNC16(bD0,      w1P);
    CP_ASYNC16(bD0 + 16, w1P + 16);
    CP_COMMIT();
    uint4 rsA = *(const uint4*)(sRowBase);       // 8 halfs
    uint4 rsB = *(const uint4*)(sRowBase + 8);   // 8 halfs

    for (int t = 0; t < NKT; t++) {
        int cur = t & 1, nxt = cur ^ 1;
        bool more = (t + 1 < NKT);
        int th0 = t * KT;

        // A fill: prefetched s-row + fresh e2-row, HMAX2 merge
        {
            const __half* pe = e2RowBase + th0;
            uint4 e0 = *(const uint4*)(pe);
            uint4 e1 = *(const uint4*)(pe + 8);
            uint4 r0, r1;
            r0.x = hmax2u(rsA.x, e0.x); r0.y = hmax2u(rsA.y, e0.y);
            r0.z = hmax2u(rsA.z, e0.z); r0.w = hmax2u(rsA.w, e0.w);
            r1.x = hmax2u(rsB.x, e1.x); r1.y = hmax2u(rsB.y, e1.y);
            r1.z = hmax2u(rsB.z, e1.z); r1.w = hmax2u(rsB.w, e1.w);
            *(uint4*)&aH[am][ac0]     = r0;
            *(uint4*)&aH[am][ac0 + 8] = r1;
        }
        if (more) {
            const char* hp = w1P + (t + 1) * (KT * 2);
            uint32_t hd = bD0 + (uint32_t)nxt * stgStride;
            CP_ASYNC16(hd,      hp);
            CP_ASYNC16(hd + 16, hp + 16);
            CP_COMMIT();
            CP_WAIT1();
        } else {
            CP_WAIT0();
        }
        __syncthreads();

        if (more) {
            const __half* ps = sRowBase + (t + 1) * KT;
            rsA = *(const uint4*)(ps);
            rsB = *(const uint4*)(ps + 8);
        }

        uint32_t bB = bBase + (uint32_t)cur * stgStride;
#pragma unroll
        for (int ks = 0; ks < 2; ks++) {
            uint32_t kOff = (uint32_t)ks * 32u;
            uint32_t A[2][4];
#pragma unroll
            for (int mt = 0; mt < 2; mt++) {
                uint32_t row = (uint32_t)(wm * 32 + mt * 16) + aRow;
                uint32_t off = row * (LDS_A * 2) + kOff + aCol;
                LDSM_X4(A[mt][0], A[mt][1], A[mt][2], A[mt][3], aBase + off);
            }
#pragma unroll
            for (int np = 0; np < 4; np++) {
                uint32_t nrow = (uint32_t)(wn * 64 + np * 16) + bRow;
                uint32_t off = nrow * (LDS_A * 2) + kOff + bCol;
                uint32_t B[4];
                LDSM_X4(B[0], B[1], B[2], B[3], bB + off);
#pragma unroll
                for (int mt = 0; mt < 2; mt++) {
#pragma unroll
                    for (int h = 0; h < 2; h++) {
                        mma_fp16(acc[mt][np * 2 + h], A[mt], &B[h * 2]);
                    }
                }
            }
        }
        __syncthreads();
    }

    // epilogue: relu(acc + b1) dot W2, reduce over n
    int gq = lane >> 2;
    int gr = lane & 3;
#pragma unroll
    for (int mt = 0; mt < 2; mt++) {
        float p0 = 0.f, p1 = 0.f;
#pragma unroll
        for (int nt = 0; nt < 8; nt++) {
            int col = wn * 64 + nt * 8 + gr * 2;
            float b1a = sb1[col], b1b = sb1[col + 1];
            float w2a = sw2[col], w2b = sw2[col + 1];
            p0 = fmaf(fmaxf(acc[mt][nt][0] + b1a, 0.f), w2a, p0);
            p0 = fmaf(fmaxf(acc[mt][nt][1] + b1b, 0.f), w2b, p0);
            p1 = fmaf(fmaxf(acc[mt][nt][2] + b1a, 0.f), w2a, p1);
            p1 = fmaf(fmaxf(acc[mt][nt][3] + b1b, 0.f), w2b, p1);
        }
#pragma unroll
        for (int off = 1; off <= 2; off <<= 1) {
            p0 += __shfl_xor_sync(0xffffffffu, p0, off);
            p1 += __shfl_xor_sync(0xffffffffu, p1, off);
        }
        if (gr == 0) {
            int row = wm * 32 + mt * 16 + gq;
            sPart[wn][row]     = p0;
            sPart[wn][row + 8] = p1;
        }
    }
    __syncthreads();
    if (tid < MT) {
        int n = n0 + tid;
        if (n < NWIN)
            g_scores[b * NWPAD + n] = sPart[0][tid] + sPart[1][tid];
    }
}

// ---------------------------------------------------------------------------
// Partial weighted sum: grid (NH/128, NB, NSEG), 128 thr. fp16 gathers.
__global__ void __launch_bounds__(128) k_out_part() {
    int b = blockIdx.y;
    int seg = blockIdx.z;
    int h = blockIdx.x * 128 + threadIdx.x;
    int tid = threadIdx.x;
    __shared__ float sattn[WSEG];
    __shared__ int   swn[WSEG];
    __shared__ float red[128];

    float mx = -1e30f;
    for (int n = tid; n < NWIN; n += 128)
        mx = fmaxf(mx, g_scores[b * NWPAD + n]);
    red[tid] = mx;
    __syncthreads();
    for (int s = 64; s > 0; s >>= 1) {
        if (tid < s) red[tid] = fmaxf(red[tid], red[tid + s]);
        __syncthreads();
    }
    mx = red[0];
    __syncthreads();
    float sum = 0.f;
    int j0 = seg * WSEG;
    for (int n = tid; n < NWIN; n += 128) {
        float e = __expf(g_scores[b * NWPAD + n] - mx);
        sum += e;
        int r = n - j0;
        if (r >= 0 && r < WSEG) { sattn[r] = e; swn[r] = g_win[n]; }
    }
    red[tid] = sum;
    __syncthreads();
    for (int s = 64; s > 0; s >>= 1) {
        if (tid < s) red[tid] += red[tid + s];
        __syncthreads();
    }
    float inv = 1.f / red[0];
    __syncthreads();

    const __half* tb = g_tab16 + h;
    float a0 = 0.f, a1 = 0.f;
#pragma unroll 6
    for (int j = 0; j < WSEG; j += 2) {
        int w0 = swn[j], w1 = swn[j + 1];
        const __half* p0 = tb + (size_t)(((w0 >> 16) - 1) * NB + b) * NS * NH;
        const __half* p1 = tb + (size_t)(((w1 >> 16) - 1) * NB + b) * NS * NH;
        __half m0 = __hmax(p0[(w0 & 255) * NH], p0[((w0 >> 8) & 255) * NH]);
        __half m1 = __hmax(p1[(w1 & 255) * NH], p1[((w1 >> 8) & 255) * NH]);
        a0 += sattn[j]     * __half2float(m0);
        a1 += sattn[j + 1] * __half2float(m1);
    }
    g_partial[(seg * NB + b) * NH + h] = (a0 + a1) * inv;
}

__global__ void __launch_bounds__(256) k_out_reduce(float* __restrict__ out) {
    int i = blockIdx.x * 256 + threadIdx.x;   // over NB*NH
    if (i >= NB * NH) return;
    float v = 0.f;
#pragma unroll
    for (int s = 0; s < NSEG; s++) v += g_partial[s * NB * NH + i];
    out[i] = v;
}

// ---------------------------------------------------------------------------
extern "C" void kernel_launch(void* const* d_in, const int* in_sizes, int n_in,
                              void* d_out, int out_size) {
    const float* lstm = (const float*)d_in[0];
    const float* W1   = (const float*)d_in[1];
    const float* b1   = (const float*)d_in[2];
    const float* W2   = (const float*)d_in[3];
    float* out = (float*)d_out;

    k_prep<<<dim3(8, NB + 2), 256>>>(lstm, W1);
    k_scores_mma<<<dim3(NWPAD / MT, NB), 256>>>(b1, W2);
    k_out_part<<<dim3(NH / 128, NB, NSEG), 128>>>();
    k_out_reduce<<<(NB * NH + 255) / 256, 256>>>(out);
}

// round 11
// speedup vs baseline: 2.6579x; 1.0234x over previous
#include <cuda_runtime.h>
#include <cuda_fp16.h>
#include <cstdint>
#include <math.h>

#define NB 32
#define NS 64
#define NH 512
#define NA 128
#define NWIN 2016
#define NWPAD 2048
#define NLEV 7          // levels 1..6 stored (level 0 unused: width>=2)
#define MT 128
#define KT 32
#define NKT (NH / KT)
#define LDS_A 40        // padded row stride (fp16) -> 80B
#define NSEG 8
#define WSEG (NWIN / NSEG)   // 252

// Scratch (static device globals — no allocation).
__device__ __half g_tab16[(NLEV - 1) * NB * NS * NH];  // fp16 max-table, 12.6 MB
__device__ float g_scores[NB * NWPAD];
__device__ int   g_win[NWPAD];                   // packed: s | e2<<8 | k<<16
__device__ __half g_w1t[NA * NH];                // W1^T fp16 (rn), [n][k]

// ---------------------------------------------------------------------------
__device__ __forceinline__ uint32_t smem_u32(const void* p) {
    uint32_t a;
    asm("{ .reg .u64 t; cvta.to.shared.u64 t, %1; cvt.u32.u64 %0, t; }" : "=r"(a) : "l"(p));
    return a;
}
#define LDSM_X4(r0, r1, r2, r3, a) \
    asm volatile("ldmatrix.sync.aligned.m8n8.x4.shared.b16 {%0,%1,%2,%3}, [%4];" \
        : "=r"(r0), "=r"(r1), "=r"(r2), "=r"(r3) : "r"(a))
#define CP_ASYNC16(dst, src) \
    asm volatile("cp.async.ca.shared.global [%0], [%1], 16;" :: "r"(dst), "l"(src))
#define CP_COMMIT() asm volatile("cp.async.commit_group;" ::: "memory")
#define CP_WAIT1()  asm volatile("cp.async.wait_group 1;" ::: "memory")
#define CP_WAIT0()  asm volatile("cp.async.wait_group 0;" ::: "memory")

__device__ __forceinline__ void mma_fp16(float* c, const uint32_t* a, const uint32_t* b) {
    asm volatile(
        "mma.sync.aligned.m16n8k16.row.col.f32.f16.f16.f32 "
        "{%0,%1,%2,%3}, {%4,%5,%6,%7}, {%8,%9}, {%0,%1,%2,%3};"
        : "+f"(c[0]), "+f"(c[1]), "+f"(c[2]), "+f"(c[3])
        : "r"(a[0]), "r"(a[1]), "r"(a[2]), "r"(a[3]), "r"(b[0]), "r"(b[1]));
}

__device__ __forceinline__ float4 f4max(float4 a, float4 b) {
    return make_float4(fmaxf(a.x, b.x), fmaxf(a.y, b.y), fmaxf(a.z, b.z), fmaxf(a.w, b.w));
}
__device__ __forceinline__ uint32_t packh2(float a, float b) {
    __half2 h = __floats2half2_rn(a, b);
    return *(uint32_t*)&h;
}
__device__ __forceinline__ uint32_t hmax2u(uint32_t a, uint32_t b) {
    __half2 r = __hmax2(*(__half2*)&a, *(__half2*)&b);
    return *(uint32_t*)&r;
}

// ---------------------------------------------------------------------------
// Prep: grid (8, NB+2), 256 threads. Also zero-inits out.
__global__ void __launch_bounds__(256) k_prep(const float* __restrict__ lstm,
                                              const float* __restrict__ W1,
                                              float* __restrict__ out) {
    int tid = threadIdx.x;
    int by = blockIdx.y, bx = blockIdx.x;

    if (by < NB) {
        int b = by, h0 = bx * 64;
        __shared__ float4 buf[2][NS][16];
        int q = tid & 15, i0 = tid >> 4;
#pragma unroll
        for (int c = 0; c < 4; c++) {
            int i = i0 + c * 16;
            buf[0][i][q] = *(const float4*)(lstm + ((size_t)(b * NS + i)) * NH + h0 + q * 4);
        }
        __syncthreads();
        int cur = 0;
        for (int k = 1; k < NLEV; k++) {
            int half = 1 << (k - 1);
            int nxt = cur ^ 1;
#pragma unroll
            for (int c = 0; c < 4; c++) {
                int i = i0 + c * 16;
                float4 v = buf[cur][i][q];
                if (i + half < NS) v = f4max(v, buf[cur][i + half][q]);
                buf[nxt][i][q] = v;
                uint2 hv;
                hv.x = packh2(v.x, v.y);
                hv.y = packh2(v.z, v.w);
                *(uint2*)(g_tab16 + ((size_t)((k - 1) * NB + b) * NS + i) * NH + h0 + q * 4) = hv;
            }
            __syncthreads();
            cur = nxt;
        }
    } else if (by == NB) {
        int gt = bx * 256 + tid;         // 0..2047
        // window table
        if (gt < NWPAD) {
            int nn = gt < NWIN ? gt : NWIN - 1;
            int w = 2;
#pragma unroll 1
            for (int ww = 3; ww <= NS; ww++) {
                int F = (129 - ww) * (ww - 2) / 2;
                if (F <= nn) w = ww;
            }
            int Fw = (129 - w) * (w - 2) / 2;
            int s = nn - Fw;
            int k = 31 - __clz(w);
            int e2 = s + w - (1 << k);
            g_win[gt] = s | (e2 << 8) | (k << 16);
        }
        // zero-init the output accumulator
        for (int i = gt; i < NB * NH; i += 2048) out[i] = 0.f;
    } else {
        int t = bx * 256 + tid;
        int n = t >> 3;
        int kc = (t & 7) * 64;
        if (n >= NA) return;
#pragma unroll 4
        for (int k = kc; k < kc + 64; k++)
            g_w1t[n * NH + k] = __float2half_rn(W1[k * NA + n]);
    }
}

// ---------------------------------------------------------------------------
// Score kernel: single-pass fp16 HMMA. Both gather rows register-prefetched,
// double-buffered A and B smem stages, ONE __syncthreads per k-tile.
__global__ void __launch_bounds__(256, 2) k_scores_mma(
    const float* __restrict__ b1, const float* __restrict__ W2)
{
    __shared__ __align__(16) __half aH[2][MT][LDS_A];
    __shared__ __align__(16) __half bH[2][NA][LDS_A];
    __shared__ float sPart[2][MT];
    __shared__ float sb1[NA], sw2[NA];
    __shared__ int s_win[MT];

    int b  = blockIdx.y;
    int n0 = blockIdx.x * MT;
    int tid  = threadIdx.x;
    int wid  = tid >> 5, lane = tid & 31;
    int wm = wid & 3, wn = wid >> 2;

    if (tid < MT) {
        int n = n0 + tid;
        s_win[tid] = g_win[n < NWIN ? n : NWIN - 1];
    }
    if (tid >= MT && tid < MT + NA) { int a = tid - MT; sb1[a] = b1[a]; sw2[a] = W2[a]; }

    float acc[2][8][4];
#pragma unroll
    for (int mt = 0; mt < 2; mt++)
#pragma unroll
        for (int nt = 0; nt < 8; nt++)
#pragma unroll
            for (int j = 0; j < 4; j++) acc[mt][nt][j] = 0.f;

    int am = tid >> 1;
    int ac0 = (tid & 1) * 16;            // half index within row
    int bn = tid >> 1;
    int bco = (tid & 1) * 32;
    const char* w1P = (const char*)g_w1t + (size_t)bn * (NH * 2) + bco;
    uint32_t bD0 = smem_u32(&bH[0][bn][0]) + bco;
    uint32_t aD0 = smem_u32(&aH[0][am][ac0]);
    const uint32_t bStride = NA * LDS_A * 2;
    const uint32_t aStride = MT * LDS_A * 2;

    __syncthreads();   // s_win ready

    uint32_t aRow = (uint32_t)(lane & 15);
    uint32_t aCol = (uint32_t)(lane >> 4) * 16u;
    uint32_t bRow = (uint32_t)((lane & 7) + ((lane >> 4) << 3));
    uint32_t bCol = (uint32_t)((lane >> 3) & 1) * 16u;
    uint32_t aBase = smem_u32(&aH[0][0][0]);
    uint32_t bBase = smem_u32(&bH[0][0][0]);

    int wi = s_win[am];
    int ws = wi & 255, we2 = (wi >> 8) & 255, wk = wi >> 16;
    const __half* gbase = g_tab16 + ((size_t)((wk - 1) * NB + b) * NS) * NH + ac0;
    const __half* sRowBase  = gbase + (size_t)ws * NH;
    const __half* e2RowBase = gbase + (size_t)we2 * NH;

    // prologue: B(0) + both rows for t=0
    CP_ASYNC16(bD0,      w1P);
    CP_ASYNC16(bD0 + 16, w1P + 16);
    CP_COMMIT();
    uint4 rsA = *(const uint4*)(sRowBase);
    uint4 rsB = *(const uint4*)(sRowBase + 8);
    uint4 reA = *(const uint4*)(e2RowBase);
    uint4 reB = *(const uint4*)(e2RowBase + 8);

    for (int t = 0; t < NKT; t++) {
        int cur = t & 1, nxt = cur ^ 1;
        bool more = (t + 1 < NKT);

        // A fill into stage cur: pure HMAX2 + STS (rows already in regs)
        {
            uint4 r0, r1;
            r0.x = hmax2u(rsA.x, reA.x); r0.y = hmax2u(rsA.y, reA.y);
            r0.z = hmax2u(rsA.z, reA.z); r0.w = hmax2u(rsA.w, reA.w);
            r1.x = hmax2u(rsB.x, reB.x); r1.y = hmax2u(rsB.y, reB.y);
            r1.z = hmax2u(rsB.z, reB.z); r1.w = hmax2u(rsB.w, reB.w);
            uint32_t ad = aD0 + (uint32_t)cur * aStride;
            *(uint4*)(uintptr_t)0;  // (no-op placeholder removed below)
            // direct smem stores
            ((uint4*)&aH[cur][am][ac0])[0] = r0;
            ((uint4*)&aH[cur][am][ac0 + 8 - 8])[0] = r0;  // overwritten correctly below
            *(uint4*)&aH[cur][am][ac0]     = r0;
            *(uint4*)&aH[cur][am][ac0 + 8] = r1;
            (void)ad;
        }
        if (more) {
            const char* hp = w1P + (t + 1) * (KT * 2);
            uint32_t hd = bD0 + (uint32_t)nxt * bStride;
            CP_ASYNC16(hd,      hp);
            CP_ASYNC16(hd + 16, hp + 16);
            CP_COMMIT();
            CP_WAIT1();
        } else {
            CP_WAIT0();
        }
        __syncthreads();   // the ONLY barrier per tile

        // prefetch both rows for t+1 (LDGs fly under the MMAs)
        if (more) {
            const __half* ps = sRowBase  + (t + 1) * KT;
            const __half* pe = e2RowBase + (t + 1) * KT;
            rsA = *(const uint4*)(ps);
            rsB = *(const uint4*)(ps + 8);
            reA = *(const uint4*)(pe);
            reB = *(const uint4*)(pe + 8);
        }

        uint32_t aB = aBase + (uint32_t)cur * aStride;
        uint32_t bB = bBase + (uint32_t)cur * bStride;
#pragma unroll
        for (int ks = 0; ks < 2; ks++) {
            uint32_t kOff = (uint32_t)ks * 32u;
            uint32_t A[2][4];
#pragma unroll
            for (int mt = 0; mt < 2; mt++) {
                uint32_t row = (uint32_t)(wm * 32 + mt * 16) + aRow;
                uint32_t off = row * (LDS_A * 2) + kOff + aCol;
                LDSM_X4(A[mt][0], A[mt][1], A[mt][2], A[mt][3], aB + off);
            }
#pragma unroll
            for (int np = 0; np < 4; np++) {
                uint32_t nrow = (uint32_t)(wn * 64 + np * 16) + bRow;
                uint32_t off = nrow * (LDS_A * 2) + kOff + bCol;
                uint32_t B[4];
                LDSM_X4(B[0], B[1], B[2], B[3], bB + off);
#pragma unroll
                for (int mt = 0; mt < 2; mt++) {
#pragma unroll
                    for (int h = 0; h < 2; h++) {
                        mma_fp16(acc[mt][np * 2 + h], A[mt], &B[h * 2]);
                    }
                }
            }
        }
    }
    __syncthreads();

    // epilogue: relu(acc + b1) dot W2, reduce over n
    int gq = lane >> 2;
    int gr = lane & 3;
#pragma unroll
    for (int mt = 0; mt < 2; mt++) {
        float p0 = 0.f, p1 = 0.f;
#pragma unroll
        for (int nt = 0; nt < 8; nt++) {
            int col = wn * 64 + nt * 8 + gr * 2;
            float b1a = sb1[col], b1b = sb1[col + 1];
            float w2a = sw2[col], w2b = sw2[col + 1];
            p0 = fmaf(fmaxf(acc[mt][nt][0] + b1a, 0.f), w2a, p0);
            p0 = fmaf(fmaxf(acc[mt][nt][1] + b1b, 0.f), w2b, p0);
            p1 = fmaf(fmaxf(acc[mt][nt][2] + b1a, 0.f), w2a, p1);
            p1 = fmaf(fmaxf(acc[mt][nt][3] + b1b, 0.f), w2b, p1);
        }
#pragma unroll
        for (int off = 1; off <= 2; off <<= 1) {
            p0 += __shfl_xor_sync(0xffffffffu, p0, off);
            p1 += __shfl_xor_sync(0xffffffffu, p1, off);
        }
        if (gr == 0) {
            int row = wm * 32 + mt * 16 + gq;
            sPart[wn][row]     = p0;
            sPart[wn][row + 8] = p1;
        }
    }
    __syncthreads();
    if (tid < MT) {
        int n = n0 + tid;
        if (n < NWIN)
            g_scores[b * NWPAD + n] = sPart[0][tid] + sPart[1][tid];
    }
}

// ---------------------------------------------------------------------------
// Partial weighted sum: grid (NH/128, NB, NSEG), 128 thr. atomicAdd into out.
__global__ void __launch_bounds__(128) k_out_part(float* __restrict__ out) {
    int b = blockIdx.y;
    int seg = blockIdx.z;
    int h = blockIdx.x * 128 + threadIdx.x;
    int tid = threadIdx.x;
    __shared__ float sattn[WSEG];
    __shared__ int   swn[WSEG];
    __shared__ float red[128];

    float mx = -1e30f;
    for (int n = tid; n < NWIN; n += 128)
        mx = fmaxf(mx, g_scores[b * NWPAD + n]);
    red[tid] = mx;
    __syncthreads();
    for (int s = 64; s > 0; s >>= 1) {
        if (tid < s) red[tid] = fmaxf(red[tid], red[tid + s]);
        __syncthreads();
    }
    mx = red[0];
    __syncthreads();
    float sum = 0.f;
    int j0 = seg * WSEG;
    for (int n = tid; n < NWIN; n += 128) {
        float e = __expf(g_scores[b * NWPAD + n] - mx);
        sum += e;
        int r = n - j0;
        if (r >= 0 && r < WSEG) { sattn[r] = e; swn[r] = g_win[n]; }
    }
    red[tid] = sum;
    __syncthreads();
    for (int s = 64; s > 0; s >>= 1) {
        if (tid < s) red[tid] += red[tid + s];
        __syncthreads();
    }
    float inv = 1.f / red[0];
    __syncthreads();

    const __half* tb = g_tab16 + h;
    float a0 = 0.f, a1 = 0.f;
#pragma unroll 6
    for (int j = 0; j < WSEG; j += 2) {
        int w0 = swn[j], w1 = swn[j + 1];
        const __half* p0 = tb + (size_t)(((w0 >> 16) - 1) * NB + b) * NS * NH;
        const __half* p1 = tb + (size_t)(((w1 >> 16) - 1) * NB + b) * NS * NH;
        __half m0 = __hmax(p0[(w0 & 255) * NH], p0[((w0 >> 8) & 255) * NH]);
        __half m1 = __hmax(p1[(w1 & 255) * NH], p1[((w1 >> 8) & 255) * NH]);
        a0 += sattn[j]     * __half2float(m0);
        a1 += sattn[j + 1] * __half2float(m1);
    }
    atomicAdd(&out[b * NH + h], (a0 + a1) * inv);
}

// ---------------------------------------------------------------------------
extern "C" void kernel_launch(void* const* d_in, const int* in_sizes, int n_in,
                              void* d_out, int out_size) {
    const float* lstm = (const float*)d_in[0];
    const float* W1   = (const float*)d_in[1];
    const float* b1   = (const float*)d_in[2];
    const float* W2   = (const float*)d_in[3];
    float* out = (float*)d_out;

    k_prep<<<dim3(8, NB + 2), 256>>>(lstm, W1, out);
    k_scores_mma<<<dim3(NWPAD / MT, NB), 256>>>(b1, W2);
    k_out_part<<<dim3(NH / 128, NB, NSEG), 128>>>(out);
}

// round 12
// speedup vs baseline: 3.0199x; 1.1362x over previous
#include <cuda_runtime.h>
#include <cuda_fp16.h>
#include <cstdint>
#include <math.h>

#define NB 32
#define NS 64
#define NH 512
#define NA 128
#define NWIN 2016
#define NWPAD 2048
#define NLEV 7          // levels 1..6 stored (level 0 unused: width>=2)
#define MT 128
#define KT 32
#define NKT (NH / KT)
#define LDS_A 40        // padded row stride (fp16) -> 80B
#define NSEG 8
#define WSEG (NWIN / NSEG)   // 252

// Scratch (static device globals — no allocation).
__device__ __half g_tab16[(NLEV - 1) * NB * NS * NH];  // fp16 max-table, 12.6 MB
__device__ float g_scores[NB * NWPAD];
__device__ float g_attn[NB * NWPAD];             // normalized softmax weights
__device__ int   g_win[NWPAD];                   // packed: s | e2<<8 | k<<16
__device__ __half g_w1t[NA * NH];                // W1^T fp16 (rn), [n][k]

// ---------------------------------------------------------------------------
__device__ __forceinline__ uint32_t smem_u32(const void* p) {
    uint32_t a;
    asm("{ .reg .u64 t; cvta.to.shared.u64 t, %1; cvt.u32.u64 %0, t; }" : "=r"(a) : "l"(p));
    return a;
}
#define LDSM_X4(r0, r1, r2, r3, a) \
    asm volatile("ldmatrix.sync.aligned.m8n8.x4.shared.b16 {%0,%1,%2,%3}, [%4];" \
        : "=r"(r0), "=r"(r1), "=r"(r2), "=r"(r3) : "r"(a))
#define CP_ASYNC16(dst, src) \
    asm volatile("cp.async.ca.shared.global [%0], [%1], 16;" :: "r"(dst), "l"(src))
#define CP_COMMIT() asm volatile("cp.async.commit_group;" ::: "memory")
#define CP_WAIT1()  asm volatile("cp.async.wait_group 1;" ::: "memory")
#define CP_WAIT0()  asm volatile("cp.async.wait_group 0;" ::: "memory")

__device__ __forceinline__ void mma_fp16(float* c, const uint32_t* a, const uint32_t* b) {
    asm volatile(
        "mma.sync.aligned.m16n8k16.row.col.f32.f16.f16.f32 "
        "{%0,%1,%2,%3}, {%4,%5,%6,%7}, {%8,%9}, {%0,%1,%2,%3};"
        : "+f"(c[0]), "+f"(c[1]), "+f"(c[2]), "+f"(c[3])
        : "r"(a[0]), "r"(a[1]), "r"(a[2]), "r"(a[3]), "r"(b[0]), "r"(b[1]));
}

__device__ __forceinline__ float4 f4max(float4 a, float4 b) {
    return make_float4(fmaxf(a.x, b.x), fmaxf(a.y, b.y), fmaxf(a.z, b.z), fmaxf(a.w, b.w));
}
__device__ __forceinline__ uint32_t packh2(float a, float b) {
    __half2 h = __floats2half2_rn(a, b);
    return *(uint32_t*)&h;
}
__device__ __forceinline__ uint32_t hmax2u(uint32_t a, uint32_t b) {
    __half2 r = __hmax2(*(__half2*)&a, *(__half2*)&b);
    return *(uint32_t*)&r;
}

// ---------------------------------------------------------------------------
// Prep: grid (8, NB+2), 256 threads.
//   by <  NB   : sparse max-table (fp16 stores)
//   by == NB   : window table + zero out
//   by == NB+1 : W1^T fp16 convert, COALESCED loads (n = tid&127)
__global__ void __launch_bounds__(256) k_prep(const float* __restrict__ lstm,
                                              const float* __restrict__ W1,
                                              float* __restrict__ out) {
    int tid = threadIdx.x;
    int by = blockIdx.y, bx = blockIdx.x;

    if (by < NB) {
        int b = by, h0 = bx * 64;
        __shared__ float4 buf[2][NS][16];
        int q = tid & 15, i0 = tid >> 4;
#pragma unroll
        for (int c = 0; c < 4; c++) {
            int i = i0 + c * 16;
            buf[0][i][q] = *(const float4*)(lstm + ((size_t)(b * NS + i)) * NH + h0 + q * 4);
        }
        __syncthreads();
        int cur = 0;
        for (int k = 1; k < NLEV; k++) {
            int half = 1 << (k - 1);
            int nxt = cur ^ 1;
#pragma unroll
            for (int c = 0; c < 4; c++) {
                int i = i0 + c * 16;
                float4 v = buf[cur][i][q];
                if (i + half < NS) v = f4max(v, buf[cur][i + half][q]);
                buf[nxt][i][q] = v;
                uint2 hv;
                hv.x = packh2(v.x, v.y);
                hv.y = packh2(v.z, v.w);
                *(uint2*)(g_tab16 + ((size_t)((k - 1) * NB + b) * NS + i) * NH + h0 + q * 4) = hv;
            }
            __syncthreads();
            cur = nxt;
        }
    } else if (by == NB) {
        int gt = bx * 256 + tid;         // 0..2047
        if (gt < NWPAD) {
            int nn = gt < NWIN ? gt : NWIN - 1;
            int w = 2;
#pragma unroll 1
            for (int ww = 3; ww <= NS; ww++) {
                int F = (129 - ww) * (ww - 2) / 2;
                if (F <= nn) w = ww;
            }
            int Fw = (129 - w) * (w - 2) / 2;
            int s = nn - Fw;
            int k = 31 - __clz(w);
            int e2 = s + w - (1 << k);
            g_win[gt] = s | (e2 << 8) | (k << 16);
        }
        for (int i = gt; i < NB * NH; i += 2048) out[i] = 0.f;
    } else {
        // W1^T: block bx covers k in [bx*64, bx*64+64). Coalesced loads.
        int n = tid & 127;
        int kh = tid >> 7;               // 0..1
#pragma unroll 8
        for (int i = 0; i < 32; i++) {
            int k = bx * 64 + kh * 32 + i;
            g_w1t[n * NH + k] = __float2half_rn(W1[k * NA + n]);
        }
    }
}

// ---------------------------------------------------------------------------
// Score kernel: single-pass fp16 HMMA. Both gather rows register-prefetched,
// double-buffered A and B smem stages, ONE __syncthreads per k-tile.
__global__ void __launch_bounds__(256, 2) k_scores_mma(
    const float* __restrict__ b1, const float* __restrict__ W2)
{
    __shared__ __align__(16) __half aH[2][MT][LDS_A];
    __shared__ __align__(16) __half bH[2][NA][LDS_A];
    __shared__ float sPart[2][MT];
    __shared__ float sb1[NA], sw2[NA];
    __shared__ int s_win[MT];

    int b  = blockIdx.y;
    int n0 = blockIdx.x * MT;
    int tid  = threadIdx.x;
    int wid  = tid >> 5, lane = tid & 31;
    int wm = wid & 3, wn = wid >> 2;

    if (tid < MT) {
        int n = n0 + tid;
        s_win[tid] = g_win[n < NWIN ? n : NWIN - 1];
    }
    if (tid >= MT && tid < MT + NA) { int a = tid - MT; sb1[a] = b1[a]; sw2[a] = W2[a]; }

    float acc[2][8][4];
#pragma unroll
    for (int mt = 0; mt < 2; mt++)
#pragma unroll
        for (int nt = 0; nt < 8; nt++)
#pragma unroll
            for (int j = 0; j < 4; j++) acc[mt][nt][j] = 0.f;

    int am = tid >> 1;
    int ac0 = (tid & 1) * 16;
    int bn = tid >> 1;
    int bco = (tid & 1) * 32;
    const char* w1P = (const char*)g_w1t + (size_t)bn * (NH * 2) + bco;
    uint32_t bD0 = smem_u32(&bH[0][bn][0]) + bco;
    const uint32_t bStride = NA * LDS_A * 2;
    const uint32_t aStride = MT * LDS_A * 2;

    __syncthreads();   // s_win ready

    uint32_t aRow = (uint32_t)(lane & 15);
    uint32_t aCol = (uint32_t)(lane >> 4) * 16u;
    uint32_t bRow = (uint32_t)((lane & 7) + ((lane >> 4) << 3));
    uint32_t bCol = (uint32_t)((lane >> 3) & 1) * 16u;
    uint32_t aBase = smem_u32(&aH[0][0][0]);
    uint32_t bBase = smem_u32(&bH[0][0][0]);

    int wi = s_win[am];
    int ws = wi & 255, we2 = (wi >> 8) & 255, wk = wi >> 16;
    const __half* gbase = g_tab16 + ((size_t)((wk - 1) * NB + b) * NS) * NH + ac0;
    const __half* sRowBase  = gbase + (size_t)ws * NH;
    const __half* e2RowBase = gbase + (size_t)we2 * NH;

    // prologue: B(0) + both rows for t=0
    CP_ASYNC16(bD0,      w1P);
    CP_ASYNC16(bD0 + 16, w1P + 16);
    CP_COMMIT();
    uint4 rsA = *(const uint4*)(sRowBase);
    uint4 rsB = *(const uint4*)(sRowBase + 8);
    uint4 reA = *(const uint4*)(e2RowBase);
    uint4 reB = *(const uint4*)(e2RowBase + 8);

    for (int t = 0; t < NKT; t++) {
        int cur = t & 1, nxt = cur ^ 1;
        bool more = (t + 1 < NKT);

        // A fill into stage cur: pure HMAX2 + STS
        {
            uint4 r0, r1;
            r0.x = hmax2u(rsA.x, reA.x); r0.y = hmax2u(rsA.y, reA.y);
            r0.z = hmax2u(rsA.z, reA.z); r0.w = hmax2u(rsA.w, reA.w);
            r1.x = hmax2u(rsB.x, reB.x); r1.y = hmax2u(rsB.y, reB.y);
            r1.z = hmax2u(rsB.z, reB.z); r1.w = hmax2u(rsB.w, reB.w);
            *(uint4*)&aH[cur][am][ac0]     = r0;
            *(uint4*)&aH[cur][am][ac0 + 8] = r1;
        }
        if (more) {
            const char* hp = w1P + (t + 1) * (KT * 2);
            uint32_t hd = bD0 + (uint32_t)nxt * bStride;
            CP_ASYNC16(hd,      hp);
            CP_ASYNC16(hd + 16, hp + 16);
            CP_COMMIT();
            CP_WAIT1();
        } else {
            CP_WAIT0();
        }
        __syncthreads();   // the ONLY barrier per tile

        if (more) {
            const __half* ps = sRowBase  + (t + 1) * KT;
            const __half* pe = e2RowBase + (t + 1) * KT;
            rsA = *(const uint4*)(ps);
            rsB = *(const uint4*)(ps + 8);
            reA = *(const uint4*)(pe);
            reB = *(const uint4*)(pe + 8);
        }

        uint32_t aB = aBase + (uint32_t)cur * aStride;
        uint32_t bB = bBase + (uint32_t)cur * bStride;
#pragma unroll
        for (int ks = 0; ks < 2; ks++) {
            uint32_t kOff = (uint32_t)ks * 32u;
            uint32_t A[2][4];
#pragma unroll
            for (int mt = 0; mt < 2; mt++) {
                uint32_t row = (uint32_t)(wm * 32 + mt * 16) + aRow;
                uint32_t off = row * (LDS_A * 2) + kOff + aCol;
                LDSM_X4(A[mt][0], A[mt][1], A[mt][2], A[mt][3], aB + off);
            }
#pragma unroll
            for (int np = 0; np < 4; np++) {
                uint32_t nrow = (uint32_t)(wn * 64 + np * 16) + bRow;
                uint32_t off = nrow * (LDS_A * 2) + kOff + bCol;
                uint32_t B[4];
                LDSM_X4(B[0], B[1], B[2], B[3], bB + off);
#pragma unroll
                for (int mt = 0; mt < 2; mt++) {
#pragma unroll
                    for (int h = 0; h < 2; h++) {
                        mma_fp16(acc[mt][np * 2 + h], A[mt], &B[h * 2]);
                    }
                }
            }
        }
    }
    __syncthreads();

    // epilogue: relu(acc + b1) dot W2, reduce over n
    int gq = lane >> 2;
    int gr = lane & 3;
#pragma unroll
    for (int mt = 0; mt < 2; mt++) {
        float p0 = 0.f, p1 = 0.f;
#pragma unroll
        for (int nt = 0; nt < 8; nt++) {
            int col = wn * 64 + nt * 8 + gr * 2;
            float b1a = sb1[col], b1b = sb1[col + 1];
            float w2a = sw2[col], w2b = sw2[col + 1];
            p0 = fmaf(fmaxf(acc[mt][nt][0] + b1a, 0.f), w2a, p0);
            p0 = fmaf(fmaxf(acc[mt][nt][1] + b1b, 0.f), w2b, p0);
            p1 = fmaf(fmaxf(acc[mt][nt][2] + b1a, 0.f), w2a, p1);
            p1 = fmaf(fmaxf(acc[mt][nt][3] + b1b, 0.f), w2b, p1);
        }
#pragma unroll
        for (int off = 1; off <= 2; off <<= 1) {
            p0 += __shfl_xor_sync(0xffffffffu, p0, off);
            p1 += __shfl_xor_sync(0xffffffffu, p1, off);
        }
        if (gr == 0) {
            int row = wm * 32 + mt * 16 + gq;
            sPart[wn][row]     = p0;
            sPart[wn][row + 8] = p1;
        }
    }
    __syncthreads();
    if (tid < MT) {
        int n = n0 + tid;
        if (n < NWIN)
            g_scores[b * NWPAD + n] = sPart[0][tid] + sPart[1][tid];
    }
}

// ---------------------------------------------------------------------------
// Softmax: 32 CTAs, 256 thr. Writes NORMALIZED attn.
__global__ void __launch_bounds__(256) k_attn() {
    int b = blockIdx.x;
    int tid = threadIdx.x;
    __shared__ float red[256];

    float mx = -1e30f;
    for (int n = tid; n < NWIN; n += 256)
        mx = fmaxf(mx, g_scores[b * NWPAD + n]);
    red[tid] = mx;
    __syncthreads();
    for (int s = 128; s > 0; s >>= 1) {
        if (tid < s) red[tid] = fmaxf(red[tid], red[tid + s]);
        __syncthreads();
    }
    mx = red[0];
    __syncthreads();
    float sum = 0.f;
    float e[8];
#pragma unroll
    for (int c = 0; c < 8; c++) {
        int n = c * 256 + tid;
        e[c] = (n < NWIN) ? __expf(g_scores[b * NWPAD + n] - mx) : 0.f;
        sum += e[c];
    }
    red[tid] = sum;
    __syncthreads();
    for (int s = 128; s > 0; s >>= 1) {
        if (tid < s) red[tid] += red[tid + s];
        __syncthreads();
    }
    float inv = 1.f / red[0];
#pragma unroll
    for (int c = 0; c < 8; c++) {
        int n = c * 256 + tid;
        if (n < NWPAD) g_attn[b * NWPAD + n] = e[c] * inv;
    }
}

// ---------------------------------------------------------------------------
// Partial weighted sum: grid (NH/128, NB, NSEG), 128 thr. No softmax here.
__global__ void __launch_bounds__(128) k_out_part(float* __restrict__ out) {
    int b = blockIdx.y;
    int seg = blockIdx.z;
    int h = blockIdx.x * 128 + threadIdx.x;
    int tid = threadIdx.x;
    __shared__ float sattn[WSEG];
    __shared__ int   swn[WSEG];

    int j0 = seg * WSEG;
    for (int r = tid; r < WSEG; r += 128) {
        sattn[r] = g_attn[b * NWPAD + j0 + r];
        swn[r]   = g_win[j0 + r];
    }
    __syncthreads();

    const __half* tb = g_tab16 + h;
    float a0 = 0.f, a1 = 0.f;
#pragma unroll 6
    for (int j = 0; j < WSEG; j += 2) {
        int w0 = swn[j], w1 = swn[j + 1];
        const __half* p0 = tb + (size_t)(((w0 >> 16) - 1) * NB + b) * NS * NH;
        const __half* p1 = tb + (size_t)(((w1 >> 16) - 1) * NB + b) * NS * NH;
        __half m0 = __hmax(p0[(w0 & 255) * NH], p0[((w0 >> 8) & 255) * NH]);
        __half m1 = __hmax(p1[(w1 & 255) * NH], p1[((w1 >> 8) & 255) * NH]);
        a0 += sattn[j]     * __half2float(m0);
        a1 += sattn[j + 1] * __half2float(m1);
    }
    atomicAdd(&out[b * NH + h], a0 + a1);
}

// ---------------------------------------------------------------------------
extern "C" void kernel_launch(void* const* d_in, const int* in_sizes, int n_in,
                              void* d_out, int out_size) {
    const float* lstm = (const float*)d_in[0];
    const float* W1   = (const float*)d_in[1];
    const float* b1   = (const float*)d_in[2];
    const float* W2   = (const float*)d_in[3];
    float* out = (float*)d_out;

    k_prep<<<dim3(8, NB + 2), 256>>>(lstm, W1, out);
    k_scores_mma<<<dim3(NWPAD / MT, NB), 256>>>(b1, W2);
    k_attn<<<NB, 256>>>();
    k_out_part<<<dim3(NH / 128, NB, NSEG), 128>>>(out);
}

// round 13
// speedup vs baseline: 3.2969x; 1.0918x over previous
#include <cuda_runtime.h>
#include <cuda_fp16.h>
#include <cstdint>
#include <math.h>

#define NB 32
#define NS 64
#define NH 512
#define NA 128
#define NWIN 2016
#define NWPAD 2048
#define NLEV 7          // levels 1..6 stored (level 0 unused: width>=2)
#define MT 128
#define KT 32
#define NKT (NH / KT)
#define LDS_A 40        // padded row stride (fp16) -> 80B
#define NSEG 8
#define WSEG (NWIN / NSEG)   // 252

// Scratch (static device globals — no allocation).
__device__ __half g_tab16[(NLEV - 1) * NB * NS * NH];  // fp16 max-table, 12.6 MB
__device__ float g_scores[NB * NWPAD];
__device__ float g_attn[NB * NWPAD];             // normalized softmax weights
__device__ int   g_win[NWPAD];                   // packed: s | e2<<8 | k<<16
__device__ int2  g_woff[NWPAD];                  // precomputed element offsets (s,e2)
__device__ __half g_w1t[NA * NH];                // W1^T fp16 (rn), [n][k]

// ---------------------------------------------------------------------------
__device__ __forceinline__ uint32_t smem_u32(const void* p) {
    uint32_t a;
    asm("{ .reg .u64 t; cvta.to.shared.u64 t, %1; cvt.u32.u64 %0, t; }" : "=r"(a) : "l"(p));
    return a;
}
#define LDSM_X4(r0, r1, r2, r3, a) \
    asm volatile("ldmatrix.sync.aligned.m8n8.x4.shared.b16 {%0,%1,%2,%3}, [%4];" \
        : "=r"(r0), "=r"(r1), "=r"(r2), "=r"(r3) : "r"(a))
#define CP_ASYNC16(dst, src) \
    asm volatile("cp.async.ca.shared.global [%0], [%1], 16;" :: "r"(dst), "l"(src))
#define CP_COMMIT() asm volatile("cp.async.commit_group;" ::: "memory")
#define CP_WAIT1()  asm volatile("cp.async.wait_group 1;" ::: "memory")
#define CP_WAIT0()  asm volatile("cp.async.wait_group 0;" ::: "memory")

__device__ __forceinline__ void mma_fp16(float* c, const uint32_t* a, const uint32_t* b) {
    asm volatile(
        "mma.sync.aligned.m16n8k16.row.col.f32.f16.f16.f32 "
        "{%0,%1,%2,%3}, {%4,%5,%6,%7}, {%8,%9}, {%0,%1,%2,%3};"
        : "+f"(c[0]), "+f"(c[1]), "+f"(c[2]), "+f"(c[3])
        : "r"(a[0]), "r"(a[1]), "r"(a[2]), "r"(a[3]), "r"(b[0]), "r"(b[1]));
}

__device__ __forceinline__ float4 f4max(float4 a, float4 b) {
    return make_float4(fmaxf(a.x, b.x), fmaxf(a.y, b.y), fmaxf(a.z, b.z), fmaxf(a.w, b.w));
}
__device__ __forceinline__ uint32_t packh2(float a, float b) {
    __half2 h = __floats2half2_rn(a, b);
    return *(uint32_t*)&h;
}
__device__ __forceinline__ uint32_t hmax2u(uint32_t a, uint32_t b) {
    __half2 r = __hmax2(*(__half2*)&a, *(__half2*)&b);
    return *(uint32_t*)&r;
}

// ---------------------------------------------------------------------------
// Prep: grid (8, NB+2), 256 threads.
__global__ void __launch_bounds__(256) k_prep(const float* __restrict__ lstm,
                                              const float* __restrict__ W1,
                                              float* __restrict__ out) {
    int tid = threadIdx.x;
    int by = blockIdx.y, bx = blockIdx.x;

    if (by < NB) {
        int b = by, h0 = bx * 64;
        __shared__ float4 buf[2][NS][16];
        int q = tid & 15, i0 = tid >> 4;
#pragma unroll
        for (int c = 0; c < 4; c++) {
            int i = i0 + c * 16;
            buf[0][i][q] = *(const float4*)(lstm + ((size_t)(b * NS + i)) * NH + h0 + q * 4);
        }
        __syncthreads();
        int cur = 0;
        for (int k = 1; k < NLEV; k++) {
            int half = 1 << (k - 1);
            int nxt = cur ^ 1;
#pragma unroll
            for (int c = 0; c < 4; c++) {
                int i = i0 + c * 16;
                float4 v = buf[cur][i][q];
                if (i + half < NS) v = f4max(v, buf[cur][i + half][q]);
                buf[nxt][i][q] = v;
                uint2 hv;
                hv.x = packh2(v.x, v.y);
                hv.y = packh2(v.z, v.w);
                *(uint2*)(g_tab16 + ((size_t)((k - 1) * NB + b) * NS + i) * NH + h0 + q * 4) = hv;
            }
            __syncthreads();
            cur = nxt;
        }
    } else if (by == NB) {
        int gt = bx * 256 + tid;         // 0..2047
        if (gt < NWPAD) {
            int nn = gt < NWIN ? gt : NWIN - 1;
            int w = 2;
#pragma unroll 1
            for (int ww = 3; ww <= NS; ww++) {
                int F = (129 - ww) * (ww - 2) / 2;
                if (F <= nn) w = ww;
            }
            int Fw = (129 - w) * (w - 2) / 2;
            int s = nn - Fw;
            int k = 31 - __clz(w);
            int e2 = s + w - (1 << k);
            g_win[gt] = s | (e2 << 8) | (k << 16);
            int lvl = (k - 1) * NB * NS * NH;
            g_woff[gt] = make_int2(lvl + s * NH, lvl + e2 * NH);
        }
        for (int i = gt; i < NB * NH; i += 2048) out[i] = 0.f;
    } else {
        // W1^T: block bx covers k in [bx*64, bx*64+64). Coalesced loads.
        int n = tid & 127;
        int kh = tid >> 7;
#pragma unroll 8
        for (int i = 0; i < 32; i++) {
            int k = bx * 64 + kh * 32 + i;
            g_w1t[n * NH + k] = __float2half_rn(W1[k * NA + n]);
        }
    }
}

// ---------------------------------------------------------------------------
// Score kernel: single-pass fp16 HMMA. Both gather rows register-prefetched,
// double-buffered A and B smem stages, ONE __syncthreads per k-tile.
__global__ void __launch_bounds__(256, 2) k_scores_mma(
    const float* __restrict__ b1, const float* __restrict__ W2)
{
    __shared__ __align__(16) __half aH[2][MT][LDS_A];
    __shared__ __align__(16) __half bH[2][NA][LDS_A];
    __shared__ float sPart[2][MT];
    __shared__ float sb1[NA], sw2[NA];
    __shared__ int s_win[MT];

    int b  = blockIdx.y;
    int n0 = blockIdx.x * MT;
    int tid  = threadIdx.x;
    int wid  = tid >> 5, lane = tid & 31;
    int wm = wid & 3, wn = wid >> 2;

    if (tid < MT) {
        int n = n0 + tid;
        s_win[tid] = g_win[n < NWIN ? n : NWIN - 1];
    }
    if (tid >= MT && tid < MT + NA) { int a = tid - MT; sb1[a] = b1[a]; sw2[a] = W2[a]; }

    float acc[2][8][4];
#pragma unroll
    for (int mt = 0; mt < 2; mt++)
#pragma unroll
        for (int nt = 0; nt < 8; nt++)
#pragma unroll
            for (int j = 0; j < 4; j++) acc[mt][nt][j] = 0.f;

    int am = tid >> 1;
    int ac0 = (tid & 1) * 16;
    int bn = tid >> 1;
    int bco = (tid & 1) * 32;
    const char* w1P = (const char*)g_w1t + (size_t)bn * (NH * 2) + bco;
    uint32_t bD0 = smem_u32(&bH[0][bn][0]) + bco;
    const uint32_t bStride = NA * LDS_A * 2;
    const uint32_t aStride = MT * LDS_A * 2;

    __syncthreads();   // s_win ready

    uint32_t aRow = (uint32_t)(lane & 15);
    uint32_t aCol = (uint32_t)(lane >> 4) * 16u;
    uint32_t bRow = (uint32_t)((lane & 7) + ((lane >> 4) << 3));
    uint32_t bCol = (uint32_t)((lane >> 3) & 1) * 16u;
    uint32_t aBase = smem_u32(&aH[0][0][0]);
    uint32_t bBase = smem_u32(&bH[0][0][0]);

    int wi = s_win[am];
    int ws = wi & 255, we2 = (wi >> 8) & 255, wk = wi >> 16;
    const __half* gbase = g_tab16 + ((size_t)((wk - 1) * NB + b) * NS) * NH + ac0;
    const __half* sRowBase  = gbase + (size_t)ws * NH;
    const __half* e2RowBase = gbase + (size_t)we2 * NH;

    // prologue: B(0) + both rows for t=0
    CP_ASYNC16(bD0,      w1P);
    CP_ASYNC16(bD0 + 16, w1P + 16);
    CP_COMMIT();
    uint4 rsA = *(const uint4*)(sRowBase);
    uint4 rsB = *(const uint4*)(sRowBase + 8);
    uint4 reA = *(const uint4*)(e2RowBase);
    uint4 reB = *(const uint4*)(e2RowBase + 8);

    for (int t = 0; t < NKT; t++) {
        int cur = t & 1, nxt = cur ^ 1;
        bool more = (t + 1 < NKT);

        {
            uint4 r0, r1;
            r0.x = hmax2u(rsA.x, reA.x); r0.y = hmax2u(rsA.y, reA.y);
            r0.z = hmax2u(rsA.z, reA.z); r0.w = hmax2u(rsA.w, reA.w);
            r1.x = hmax2u(rsB.x, reB.x); r1.y = hmax2u(rsB.y, reB.y);
            r1.z = hmax2u(rsB.z, reB.z); r1.w = hmax2u(rsB.w, reB.w);
            *(uint4*)&aH[cur][am][ac0]     = r0;
            *(uint4*)&aH[cur][am][ac0 + 8] = r1;
        }
        if (more) {
            const char* hp = w1P + (t + 1) * (KT * 2);
            uint32_t hd = bD0 + (uint32_t)nxt * bStride;
            CP_ASYNC16(hd,      hp);
            CP_ASYNC16(hd + 16, hp + 16);
            CP_COMMIT();
            CP_WAIT1();
        } else {
            CP_WAIT0();
        }
        __syncthreads();

        if (more) {
            const __half* ps = sRowBase  + (t + 1) * KT;
            const __half* pe = e2RowBase + (t + 1) * KT;
            rsA = *(const uint4*)(ps);
            rsB = *(const uint4*)(ps + 8);
            reA = *(const uint4*)(pe);
            reB = *(const uint4*)(pe + 8);
        }

        uint32_t aB = aBase + (uint32_t)cur * aStride;
        uint32_t bB = bBase + (uint32_t)cur * bStride;
#pragma unroll
        for (int ks = 0; ks < 2; ks++) {
            uint32_t kOff = (uint32_t)ks * 32u;
            uint32_t A[2][4];
#pragma unroll
            for (int mt = 0; mt < 2; mt++) {
                uint32_t row = (uint32_t)(wm * 32 + mt * 16) + aRow;
                uint32_t off = row * (LDS_A * 2) + kOff + aCol;
                LDSM_X4(A[mt][0], A[mt][1], A[mt][2], A[mt][3], aB + off);
            }
#pragma unroll
            for (int np = 0; np < 4; np++) {
                uint32_t nrow = (uint32_t)(wn * 64 + np * 16) + bRow;
                uint32_t off = nrow * (LDS_A * 2) + kOff + bCol;
                uint32_t B[4];
                LDSM_X4(B[0], B[1], B[2], B[3], bB + off);
#pragma unroll
                for (int mt = 0; mt < 2; mt++) {
#pragma unroll
                    for (int h = 0; h < 2; h++) {
                        mma_fp16(acc[mt][np * 2 + h], A[mt], &B[h * 2]);
                    }
                }
            }
        }
    }
    __syncthreads();

    // epilogue: relu(acc + b1) dot W2, reduce over n
    int gq = lane >> 2;
    int gr = lane & 3;
#pragma unroll
    for (int mt = 0; mt < 2; mt++) {
        float p0 = 0.f, p1 = 0.f;
#pragma unroll
        for (int nt = 0; nt < 8; nt++) {
            int col = wn * 64 + nt * 8 + gr * 2;
            float b1a = sb1[col], b1b = sb1[col + 1];
            float w2a = sw2[col], w2b = sw2[col + 1];
            p0 = fmaf(fmaxf(acc[mt][nt][0] + b1a, 0.f), w2a, p0);
            p0 = fmaf(fmaxf(acc[mt][nt][1] + b1b, 0.f), w2b, p0);
            p1 = fmaf(fmaxf(acc[mt][nt][2] + b1a, 0.f), w2a, p1);
            p1 = fmaf(fmaxf(acc[mt][nt][3] + b1b, 0.f), w2b, p1);
        }
#pragma unroll
        for (int off = 1; off <= 2; off <<= 1) {
            p0 += __shfl_xor_sync(0xffffffffu, p0, off);
            p1 += __shfl_xor_sync(0xffffffffu, p1, off);
        }
        if (gr == 0) {
            int row = wm * 32 + mt * 16 + gq;
            sPart[wn][row]     = p0;
            sPart[wn][row + 8] = p1;
        }
    }
    __syncthreads();
    if (tid < MT) {
        int n = n0 + tid;
        if (n < NWIN)
            g_scores[b * NWPAD + n] = sPart[0][tid] + sPart[1][tid];
    }
}

// ---------------------------------------------------------------------------
// Softmax: 32 CTAs, 256 thr. Writes NORMALIZED attn.
__global__ void __launch_bounds__(256) k_attn() {
    int b = blockIdx.x;
    int tid = threadIdx.x;
    __shared__ float red[256];

    float mx = -1e30f;
    for (int n = tid; n < NWIN; n += 256)
        mx = fmaxf(mx, g_scores[b * NWPAD + n]);
    red[tid] = mx;
    __syncthreads();
    for (int s = 128; s > 0; s >>= 1) {
        if (tid < s) red[tid] = fmaxf(red[tid], red[tid + s]);
        __syncthreads();
    }
    mx = red[0];
    __syncthreads();
    float sum = 0.f;
    float e[8];
#pragma unroll
    for (int c = 0; c < 8; c++) {
        int n = c * 256 + tid;
        e[c] = (n < NWIN) ? __expf(g_scores[b * NWPAD + n] - mx) : 0.f;
        sum += e[c];
    }
    red[tid] = sum;
    __syncthreads();
    for (int s = 128; s > 0; s >>= 1) {
        if (tid < s) red[tid] += red[tid + s];
        __syncthreads();
    }
    float inv = 1.f / red[0];
#pragma unroll
    for (int c = 0; c < 8; c++) {
        int n = c * 256 + tid;
        if (n < NWPAD) g_attn[b * NWPAD + n] = e[c] * inv;
    }
}

// ---------------------------------------------------------------------------
// Partial weighted sum: grid (NB, NSEG), 128 thr, 4 h per thread.
// Precomputed offsets; two uint2 (4-half) gathers per window.
__global__ void __launch_bounds__(128) k_out_part(float* __restrict__ out) {
    int b = blockIdx.x;
    int seg = blockIdx.y;
    int tid = threadIdx.x;
    int h0 = tid * 4;
    __shared__ float sattn[WSEG];
    __shared__ int2  soff[WSEG];

    int j0 = seg * WSEG;
    for (int r = tid; r < WSEG; r += 128) {
        sattn[r] = g_attn[b * NWPAD + j0 + r];
        soff[r]  = g_woff[j0 + r];
    }
    __syncthreads();

    const __half* base = g_tab16 + (size_t)b * NS * NH + h0;
    float a0 = 0.f, a1 = 0.f, a2 = 0.f, a3 = 0.f;
#pragma unroll 4
    for (int j = 0; j < WSEG; j++) {
        float at = sattn[j];
        int2 o = soff[j];
        uint2 x = *(const uint2*)(base + o.x);
        uint2 y = *(const uint2*)(base + o.y);
        uint32_t m0 = hmax2u(x.x, y.x);
        uint32_t m1 = hmax2u(x.y, y.y);
        float2 f0 = __half22float2(*(__half2*)&m0);
        float2 f1 = __half22float2(*(__half2*)&m1);
        a0 = fmaf(at, f0.x, a0);
        a1 = fmaf(at, f0.y, a1);
        a2 = fmaf(at, f1.x, a2);
        a3 = fmaf(at, f1.y, a3);
    }
    float* op = out + b * NH + h0;
    atomicAdd(op,     a0);
    atomicAdd(op + 1, a1);
    atomicAdd(op + 2, a2);
    atomicAdd(op + 3, a3);
}

// ---------------------------------------------------------------------------
extern "C" void kernel_launch(void* const* d_in, const int* in_sizes, int n_in,
                              void* d_out, int out_size) {
    const float* lstm = (const float*)d_in[0];
    const float* W1   = (const float*)d_in[1];
    const float* b1   = (const float*)d_in[2];
    const float* W2   = (const float*)d_in[3];
    float* out = (float*)d_out;

    k_prep<<<dim3(8, NB + 2), 256>>>(lstm, W1, out);
    k_scores_mma<<<dim3(NWPAD / MT, NB), 256>>>(b1, W2);
    k_attn<<<NB, 256>>>();
    k_out_part<<<dim3(NB, NSEG), 128>>>(out);
}

// round 14
// speedup vs baseline: 3.4802x; 1.0556x over previous
#include <cuda_runtime.h>
#include <cuda_fp16.h>
#include <cstdint>
#include <math.h>

#define NB 32
#define NS 64
#define NH 512
#define NA 128
#define NWIN 2016
#define NWPAD 2048
#define NLEV 7          // levels 1..6 stored (level 0 unused: width>=2)
#define MT 128
#define KT 32
#define NKT (NH / KT)
#define LDS_A 40        // padded row stride (fp16) -> 80B
#define NSEG 16
#define WSEG (NWIN / NSEG)   // 126

// Scratch (static device globals — no allocation).
__device__ __half g_tab16[(NLEV - 1) * NB * NS * NH];  // fp16 max-table, 12.6 MB
__device__ float g_scores[NB * NWPAD];
__device__ float g_attn[NB * NWPAD];             // normalized softmax weights
__device__ int   g_win[NWPAD];                   // packed: s | e2<<8 | k<<16
__device__ int2  g_woff[NWPAD];                  // precomputed element offsets (s,e2)
__device__ __half g_w1t[NA * NH];                // W1^T fp16 (rn), [n][k]

// ---------------------------------------------------------------------------
__device__ __forceinline__ uint32_t smem_u32(const void* p) {
    uint32_t a;
    asm("{ .reg .u64 t; cvta.to.shared.u64 t, %1; cvt.u32.u64 %0, t; }" : "=r"(a) : "l"(p));
    return a;
}
#define LDSM_X4(r0, r1, r2, r3, a) \
    asm volatile("ldmatrix.sync.aligned.m8n8.x4.shared.b16 {%0,%1,%2,%3}, [%4];" \
        : "=r"(r0), "=r"(r1), "=r"(r2), "=r"(r3) : "r"(a))
#define CP_ASYNC16(dst, src) \
    asm volatile("cp.async.ca.shared.global [%0], [%1], 16;" :: "r"(dst), "l"(src))
#define CP_COMMIT() asm volatile("cp.async.commit_group;" ::: "memory")
#define CP_WAIT1()  asm volatile("cp.async.wait_group 1;" ::: "memory")
#define CP_WAIT0()  asm volatile("cp.async.wait_group 0;" ::: "memory")

__device__ __forceinline__ void mma_fp16(float* c, const uint32_t* a, const uint32_t* b) {
    asm volatile(
        "mma.sync.aligned.m16n8k16.row.col.f32.f16.f16.f32 "
        "{%0,%1,%2,%3}, {%4,%5,%6,%7}, {%8,%9}, {%0,%1,%2,%3};"
        : "+f"(c[0]), "+f"(c[1]), "+f"(c[2]), "+f"(c[3])
        : "r"(a[0]), "r"(a[1]), "r"(a[2]), "r"(a[3]), "r"(b[0]), "r"(b[1]));
}

__device__ __forceinline__ float4 f4max(float4 a, float4 b) {
    return make_float4(fmaxf(a.x, b.x), fmaxf(a.y, b.y), fmaxf(a.z, b.z), fmaxf(a.w, b.w));
}
__device__ __forceinline__ uint32_t packh2(float a, float b) {
    __half2 h = __floats2half2_rn(a, b);
    return *(uint32_t*)&h;
}
__device__ __forceinline__ uint32_t hmax2u(uint32_t a, uint32_t b) {
    __half2 r = __hmax2(*(__half2*)&a, *(__half2*)&b);
    return *(uint32_t*)&r;
}

// ---------------------------------------------------------------------------
// Prep: grid (8, NB+2), 256 threads.
__global__ void __launch_bounds__(256) k_prep(const float* __restrict__ lstm,
                                              const float* __restrict__ W1,
                                              float* __restrict__ out) {
    int tid = threadIdx.x;
    int by = blockIdx.y, bx = blockIdx.x;

    if (by < NB) {
        int b = by, h0 = bx * 64;
        __shared__ float4 buf[2][NS][16];
        int q = tid & 15, i0 = tid >> 4;
#pragma unroll
        for (int c = 0; c < 4; c++) {
            int i = i0 + c * 16;
            buf[0][i][q] = *(const float4*)(lstm + ((size_t)(b * NS + i)) * NH + h0 + q * 4);
        }
        __syncthreads();
        int cur = 0;
        for (int k = 1; k < NLEV; k++) {
            int half = 1 << (k - 1);
            int nxt = cur ^ 1;
#pragma unroll
            for (int c = 0; c < 4; c++) {
                int i = i0 + c * 16;
                float4 v = buf[cur][i][q];
                if (i + half < NS) v = f4max(v, buf[cur][i + half][q]);
                buf[nxt][i][q] = v;
                uint2 hv;
                hv.x = packh2(v.x, v.y);
                hv.y = packh2(v.z, v.w);
                *(uint2*)(g_tab16 + ((size_t)((k - 1) * NB + b) * NS + i) * NH + h0 + q * 4) = hv;
            }
            __syncthreads();
            cur = nxt;
        }
    } else if (by == NB) {
        int gt = bx * 256 + tid;         // 0..2047
        if (gt < NWPAD) {
            int nn = gt < NWIN ? gt : NWIN - 1;
            int w = 2;
#pragma unroll 1
            for (int ww = 3; ww <= NS; ww++) {
                int F = (129 - ww) * (ww - 2) / 2;
                if (F <= nn) w = ww;
            }
            int Fw = (129 - w) * (w - 2) / 2;
            int s = nn - Fw;
            int k = 31 - __clz(w);
            int e2 = s + w - (1 << k);
            g_win[gt] = s | (e2 << 8) | (k << 16);
            int lvl = (k - 1) * NB * NS * NH;
            g_woff[gt] = make_int2(lvl + s * NH, lvl + e2 * NH);
        }
        for (int i = gt; i < NB * NH; i += 2048) out[i] = 0.f;
    } else {
        // W1^T: block bx covers k in [bx*64, bx*64+64). Coalesced loads.
        int n = tid & 127;
        int kh = tid >> 7;
#pragma unroll 8
        for (int i = 0; i < 32; i++) {
            int k = bx * 64 + kh * 32 + i;
            g_w1t[n * NH + k] = __float2half_rn(W1[k * NA + n]);
        }
    }
}

// ---------------------------------------------------------------------------
// Score kernel: single-pass fp16 HMMA. Both gather rows register-prefetched,
// double-buffered A and B smem stages, ONE __syncthreads per k-tile.
__global__ void __launch_bounds__(256, 2) k_scores_mma(
    const float* __restrict__ b1, const float* __restrict__ W2)
{
    __shared__ __align__(16) __half aH[2][MT][LDS_A];
    __shared__ __align__(16) __half bH[2][NA][LDS_A];
    __shared__ float sPart[2][MT];
    __shared__ float sb1[NA], sw2[NA];
    __shared__ int s_win[MT];

    int b  = blockIdx.y;
    int n0 = blockIdx.x * MT;
    int tid  = threadIdx.x;
    int wid  = tid >> 5, lane = tid & 31;
    int wm = wid & 3, wn = wid >> 2;

    if (tid < MT) {
        int n = n0 + tid;
        s_win[tid] = g_win[n < NWIN ? n : NWIN - 1];
    }
    if (tid >= MT && tid < MT + NA) { int a = tid - MT; sb1[a] = b1[a]; sw2[a] = W2[a]; }

    float acc[2][8][4];
#pragma unroll
    for (int mt = 0; mt < 2; mt++)
#pragma unroll
        for (int nt = 0; nt < 8; nt++)
#pragma unroll
            for (int j = 0; j < 4; j++) acc[mt][nt][j] = 0.f;

    int am = tid >> 1;
    int ac0 = (tid & 1) * 16;
    int bn = tid >> 1;
    int bco = (tid & 1) * 32;
    const char* w1P = (const char*)g_w1t + (size_t)bn * (NH * 2) + bco;
    uint32_t bD0 = smem_u32(&bH[0][bn][0]) + bco;
    const uint32_t bStride = NA * LDS_A * 2;
    const uint32_t aStride = MT * LDS_A * 2;

    __syncthreads();   // s_win ready

    uint32_t aRow = (uint32_t)(lane & 15);
    uint32_t aCol = (uint32_t)(lane >> 4) * 16u;
    uint32_t bRow = (uint32_t)((lane & 7) + ((lane >> 4) << 3));
    uint32_t bCol = (uint32_t)((lane >> 3) & 1) * 16u;
    uint32_t aBase = smem_u32(&aH[0][0][0]);
    uint32_t bBase = smem_u32(&bH[0][0][0]);

    int wi = s_win[am];
    int ws = wi & 255, we2 = (wi >> 8) & 255, wk = wi >> 16;
    const __half* gbase = g_tab16 + ((size_t)((wk - 1) * NB + b) * NS) * NH + ac0;
    const __half* sRowBase  = gbase + (size_t)ws * NH;
    const __half* e2RowBase = gbase + (size_t)we2 * NH;

    // prologue: B(0) + both rows for t=0
    CP_ASYNC16(bD0,      w1P);
    CP_ASYNC16(bD0 + 16, w1P + 16);
    CP_COMMIT();
    uint4 rsA = *(const uint4*)(sRowBase);
    uint4 rsB = *(const uint4*)(sRowBase + 8);
    uint4 reA = *(const uint4*)(e2RowBase);
    uint4 reB = *(const uint4*)(e2RowBase + 8);

    for (int t = 0; t < NKT; t++) {
        int cur = t & 1, nxt = cur ^ 1;
        bool more = (t + 1 < NKT);

        {
            uint4 r0, r1;
            r0.x = hmax2u(rsA.x, reA.x); r0.y = hmax2u(rsA.y, reA.y);
            r0.z = hmax2u(rsA.z, reA.z); r0.w = hmax2u(rsA.w, reA.w);
            r1.x = hmax2u(rsB.x, reB.x); r1.y = hmax2u(rsB.y, reB.y);
            r1.z = hmax2u(rsB.z, reB.z); r1.w = hmax2u(rsB.w, reB.w);
            *(uint4*)&aH[cur][am][ac0]     = r0;
            *(uint4*)&aH[cur][am][ac0 + 8] = r1;
        }
        if (more) {
            const char* hp = w1P + (t + 1) * (KT * 2);
            uint32_t hd = bD0 + (uint32_t)nxt * bStride;
            CP_ASYNC16(hd,      hp);
            CP_ASYNC16(hd + 16, hp + 16);
            CP_COMMIT();
            CP_WAIT1();
        } else {
            CP_WAIT0();
        }
        __syncthreads();

        if (more) {
            const __half* ps = sRowBase  + (t + 1) * KT;
            const __half* pe = e2RowBase + (t + 1) * KT;
            rsA = *(const uint4*)(ps);
            rsB = *(const uint4*)(ps + 8);
            reA = *(const uint4*)(pe);
            reB = *(const uint4*)(pe + 8);
        }

        uint32_t aB = aBase + (uint32_t)cur * aStride;
        uint32_t bB = bBase + (uint32_t)cur * bStride;
#pragma unroll
        for (int ks = 0; ks < 2; ks++) {
            uint32_t kOff = (uint32_t)ks * 32u;
            uint32_t A[2][4];
#pragma unroll
            for (int mt = 0; mt < 2; mt++) {
                uint32_t row = (uint32_t)(wm * 32 + mt * 16) + aRow;
                uint32_t off = row * (LDS_A * 2) + kOff + aCol;
                LDSM_X4(A[mt][0], A[mt][1], A[mt][2], A[mt][3], aB + off);
            }
#pragma unroll
            for (int np = 0; np < 4; np++) {
                uint32_t nrow = (uint32_t)(wn * 64 + np * 16) + bRow;
                uint32_t off = nrow * (LDS_A * 2) + kOff + bCol;
                uint32_t B[4];
                LDSM_X4(B[0], B[1], B[2], B[3], bB + off);
#pragma unroll
                for (int mt = 0; mt < 2; mt++) {
#pragma unroll
                    for (int h = 0; h < 2; h++) {
                        mma_fp16(acc[mt][np * 2 + h], A[mt], &B[h * 2]);
                    }
                }
            }
        }
    }
    __syncthreads();

    // epilogue: relu(acc + b1) dot W2, reduce over n
    int gq = lane >> 2;
    int gr = lane & 3;
#pragma unroll
    for (int mt = 0; mt < 2; mt++) {
        float p0 = 0.f, p1 = 0.f;
#pragma unroll
        for (int nt = 0; nt < 8; nt++) {
            int col = wn * 64 + nt * 8 + gr * 2;
            float b1a = sb1[col], b1b = sb1[col + 1];
            float w2a = sw2[col], w2b = sw2[col + 1];
            p0 = fmaf(fmaxf(acc[mt][nt][0] + b1a, 0.f), w2a, p0);
            p0 = fmaf(fmaxf(acc[mt][nt][1] + b1b, 0.f), w2b, p0);
            p1 = fmaf(fmaxf(acc[mt][nt][2] + b1a, 0.f), w2a, p1);
            p1 = fmaf(fmaxf(acc[mt][nt][3] + b1b, 0.f), w2b, p1);
        }
#pragma unroll
        for (int off = 1; off <= 2; off <<= 1) {
            p0 += __shfl_xor_sync(0xffffffffu, p0, off);
            p1 += __shfl_xor_sync(0xffffffffu, p1, off);
        }
        if (gr == 0) {
            int row = wm * 32 + mt * 16 + gq;
            sPart[wn][row]     = p0;
            sPart[wn][row + 8] = p1;
        }
    }
    __syncthreads();
    if (tid < MT) {
        int n = n0 + tid;
        if (n < NWIN)
            g_scores[b * NWPAD + n] = sPart[0][tid] + sPart[1][tid];
    }
}

// ---------------------------------------------------------------------------
// Softmax: 32 CTAs, 256 thr. Writes NORMALIZED attn.
__global__ void __launch_bounds__(256) k_attn() {
    int b = blockIdx.x;
    int tid = threadIdx.x;
    __shared__ float red[256];

    float mx = -1e30f;
    for (int n = tid; n < NWIN; n += 256)
        mx = fmaxf(mx, g_scores[b * NWPAD + n]);
    red[tid] = mx;
    __syncthreads();
    for (int s = 128; s > 0; s >>= 1) {
        if (tid < s) red[tid] = fmaxf(red[tid], red[tid + s]);
        __syncthreads();
    }
    mx = red[0];
    __syncthreads();
    float sum = 0.f;
    float e[8];
#pragma unroll
    for (int c = 0; c < 8; c++) {
        int n = c * 256 + tid;
        e[c] = (n < NWIN) ? __expf(g_scores[b * NWPAD + n] - mx) : 0.f;
        sum += e[c];
    }
    red[tid] = sum;
    __syncthreads();
    for (int s = 128; s > 0; s >>= 1) {
        if (tid < s) red[tid] += red[tid + s];
        __syncthreads();
    }
    float inv = 1.f / red[0];
#pragma unroll
    for (int c = 0; c < 8; c++) {
        int n = c * 256 + tid;
        if (n < NWPAD) g_attn[b * NWPAD + n] = e[c] * inv;
    }
}

// ---------------------------------------------------------------------------
// Partial weighted sum: grid (NB, NSEG=16), 256 thr, 2 h per thread,
// j unrolled x2 -> MLP 4 per thread.
__global__ void __launch_bounds__(256) k_out_part(float* __restrict__ out) {
    int b = blockIdx.x;
    int seg = blockIdx.y;
    int tid = threadIdx.x;
    int h0 = tid * 2;
    __shared__ float sattn[WSEG];
    __shared__ int2  soff[WSEG];

    int j0 = seg * WSEG;
    if (tid < WSEG) {
        sattn[tid] = g_attn[b * NWPAD + j0 + tid];
        soff[tid]  = g_woff[j0 + tid];
    }
    __syncthreads();

    const __half* base = g_tab16 + (size_t)b * NS * NH + h0;
    float a0 = 0.f, a1 = 0.f, b0 = 0.f, b1v = 0.f;
#pragma unroll 3
    for (int j = 0; j < WSEG - 1; j += 2) {
        float at0 = sattn[j], at1 = sattn[j + 1];
        int2 o0 = soff[j], o1 = soff[j + 1];
        uint32_t x0 = *(const uint32_t*)(base + o0.x);
        uint32_t y0 = *(const uint32_t*)(base + o0.y);
        uint32_t x1 = *(const uint32_t*)(base + o1.x);
        uint32_t y1 = *(const uint32_t*)(base + o1.y);
        uint32_t m0 = hmax2u(x0, y0);
        uint32_t m1 = hmax2u(x1, y1);
        float2 f0 = __half22float2(*(__half2*)&m0);
        float2 f1 = __half22float2(*(__half2*)&m1);
        a0 = fmaf(at0, f0.x, a0);
        a1 = fmaf(at0, f0.y, a1);
        b0 = fmaf(at1, f1.x, b0);
        b1v = fmaf(at1, f1.y, b1v);
    }
    // WSEG=126 is even; no tail needed. (guard for safety)
#if (WSEG & 1)
    {
        int j = WSEG - 1;
        float at = sattn[j];
        int2 o = soff[j];
        uint32_t x = *(const uint32_t*)(base + o.x);
        uint32_t y = *(const uint32_t*)(base + o.y);
        uint32_t m = hmax2u(x, y);
        float2 f = __half22float2(*(__half2*)&m);
        a0 = fmaf(at, f.x, a0);
        a1 = fmaf(at, f.y, a1);
    }
#endif
    float* op = out + b * NH + h0;
    atomicAdd(op,     a0 + b0);
    atomicAdd(op + 1, a1 + b1v);
}

// ---------------------------------------------------------------------------
extern "C" void kernel_launch(void* const* d_in, const int* in_sizes, int n_in,
                              void* d_out, int out_size) {
    const float* lstm = (const float*)d_in[0];
    const float* W1   = (const float*)d_in[1];
    const float* b1   = (const float*)d_in[2];
    const float* W2   = (const float*)d_in[3];
    float* out = (float*)d_out;

    k_prep<<<dim3(8, NB + 2), 256>>>(lstm, W1, out);
    k_scores_mma<<<dim3(NWPAD / MT, NB), 256>>>(b1, W2);
    k_attn<<<NB, 256>>>();
    k_out_part<<<dim3(NB, NSEG), 256>>>(out);
}

// round 15
// speedup vs baseline: 3.5751x; 1.0273x over previous
#include <cuda_runtime.h>
#include <cuda_fp16.h>
#include <cstdint>
#include <math.h>

#define NB 32
#define NS 64
#define NH 512
#define NA 128
#define NWIN 2016
#define NWPAD 2048
#define NLEV 7          // levels 1..6 stored (level 0 unused: width>=2)
#define MT 128
#define KT 32
#define NKT (NH / KT)
#define LDS_A 40        // padded row stride (fp16) -> 80B
#define NSEG 32
#define WSEG (NWPAD / NSEG)   // 64 (padded windows have attn==0)

// Scratch (static device globals — no allocation).
__device__ __half g_tab16[(NLEV - 1) * NB * NS * NH];  // fp16 max-table, 12.6 MB
__device__ float g_scores[NB * NWPAD];
__device__ float g_attn[NB * NWPAD];             // normalized softmax weights
__device__ int   g_win[NWPAD];                   // packed: s | e2<<8 | k<<16
__device__ int2  g_woff[NWPAD];                  // precomputed element offsets (s,e2)
__device__ __half g_w1t[NA * NH];                // W1^T fp16 (rn), [n][k]

// ---------------------------------------------------------------------------
__device__ __forceinline__ uint32_t smem_u32(const void* p) {
    uint32_t a;
    asm("{ .reg .u64 t; cvta.to.shared.u64 t, %1; cvt.u32.u64 %0, t; }" : "=r"(a) : "l"(p));
    return a;
}
#define LDSM_X4(r0, r1, r2, r3, a) \
    asm volatile("ldmatrix.sync.aligned.m8n8.x4.shared.b16 {%0,%1,%2,%3}, [%4];" \
        : "=r"(r0), "=r"(r1), "=r"(r2), "=r"(r3) : "r"(a))
#define CP_ASYNC16(dst, src) \
    asm volatile("cp.async.ca.shared.global [%0], [%1], 16;" :: "r"(dst), "l"(src))
#define CP_COMMIT() asm volatile("cp.async.commit_group;" ::: "memory")
#define CP_WAIT1()  asm volatile("cp.async.wait_group 1;" ::: "memory")
#define CP_WAIT0()  asm volatile("cp.async.wait_group 0;" ::: "memory")

__device__ __forceinline__ void mma_fp16(float* c, const uint32_t* a, const uint32_t* b) {
    asm volatile(
        "mma.sync.aligned.m16n8k16.row.col.f32.f16.f16.f32 "
        "{%0,%1,%2,%3}, {%4,%5,%6,%7}, {%8,%9}, {%0,%1,%2,%3};"
        : "+f"(c[0]), "+f"(c[1]), "+f"(c[2]), "+f"(c[3])
        : "r"(a[0]), "r"(a[1]), "r"(a[2]), "r"(a[3]), "r"(b[0]), "r"(b[1]));
}

__device__ __forceinline__ float4 f4max(float4 a, float4 b) {
    return make_float4(fmaxf(a.x, b.x), fmaxf(a.y, b.y), fmaxf(a.z, b.z), fmaxf(a.w, b.w));
}
__device__ __forceinline__ uint32_t packh2(float a, float b) {
    __half2 h = __floats2half2_rn(a, b);
    return *(uint32_t*)&h;
}
__device__ __forceinline__ uint32_t hmax2u(uint32_t a, uint32_t b) {
    __half2 r = __hmax2(*(__half2*)&a, *(__half2*)&b);
    return *(uint32_t*)&r;
}

// ---------------------------------------------------------------------------
// Prep: grid (8, NB+2), 256 threads.
__global__ void __launch_bounds__(256) k_prep(const float* __restrict__ lstm,
                                              const float* __restrict__ W1,
                                              float* __restrict__ out) {
    int tid = threadIdx.x;
    int by = blockIdx.y, bx = blockIdx.x;

    if (by < NB) {
        int b = by, h0 = bx * 64;
        __shared__ float4 buf[2][NS][16];
        int q = tid & 15, i0 = tid >> 4;
#pragma unroll
        for (int c = 0; c < 4; c++) {
            int i = i0 + c * 16;
            buf[0][i][q] = *(const float4*)(lstm + ((size_t)(b * NS + i)) * NH + h0 + q * 4);
        }
        __syncthreads();
        int cur = 0;
        for (int k = 1; k < NLEV; k++) {
            int half = 1 << (k - 1);
            int nxt = cur ^ 1;
#pragma unroll
            for (int c = 0; c < 4; c++) {
                int i = i0 + c * 16;
                float4 v = buf[cur][i][q];
                if (i + half < NS) v = f4max(v, buf[cur][i + half][q]);
                buf[nxt][i][q] = v;
                uint2 hv;
                hv.x = packh2(v.x, v.y);
                hv.y = packh2(v.z, v.w);
                *(uint2*)(g_tab16 + ((size_t)((k - 1) * NB + b) * NS + i) * NH + h0 + q * 4) = hv;
            }
            __syncthreads();
            cur = nxt;
        }
    } else if (by == NB) {
        int gt = bx * 256 + tid;         // 0..2047
        if (gt < NWPAD) {
            int nn = gt < NWIN ? gt : NWIN - 1;
            int w = 2;
#pragma unroll 1
            for (int ww = 3; ww <= NS; ww++) {
                int F = (129 - ww) * (ww - 2) / 2;
                if (F <= nn) w = ww;
            }
            int Fw = (129 - w) * (w - 2) / 2;
            int s = nn - Fw;
            int k = 31 - __clz(w);
            int e2 = s + w - (1 << k);
            g_win[gt] = s | (e2 << 8) | (k << 16);
            int lvl = (k - 1) * NB * NS * NH;
            g_woff[gt] = make_int2(lvl + s * NH, lvl + e2 * NH);
        }
        for (int i = gt; i < NB * NH; i += 2048) out[i] = 0.f;
    } else {
        // W1^T: block bx covers k in [bx*64, bx*64+64). Coalesced loads.
        int n = tid & 127;
        int kh = tid >> 7;
#pragma unroll 8
        for (int i = 0; i < 32; i++) {
            int k = bx * 64 + kh * 32 + i;
            g_w1t[n * NH + k] = __float2half_rn(W1[k * NA + n]);
        }
    }
}

// ---------------------------------------------------------------------------
// Score kernel: single-pass fp16 HMMA. Both gather rows register-prefetched,
// double-buffered A and B smem stages, ONE __syncthreads per k-tile.
__global__ void __launch_bounds__(256, 2) k_scores_mma(
    const float* __restrict__ b1, const float* __restrict__ W2)
{
    __shared__ __align__(16) __half aH[2][MT][LDS_A];
    __shared__ __align__(16) __half bH[2][NA][LDS_A];
    __shared__ float sPart[2][MT];
    __shared__ float sb1[NA], sw2[NA];
    __shared__ int s_win[MT];

    int b  = blockIdx.y;
    int n0 = blockIdx.x * MT;
    int tid  = threadIdx.x;
    int wid  = tid >> 5, lane = tid & 31;
    int wm = wid & 3, wn = wid >> 2;

    if (tid < MT) {
        int n = n0 + tid;
        s_win[tid] = g_win[n < NWIN ? n : NWIN - 1];
    }
    if (tid >= MT && tid < MT + NA) { int a = tid - MT; sb1[a] = b1[a]; sw2[a] = W2[a]; }

    float acc[2][8][4];
#pragma unroll
    for (int mt = 0; mt < 2; mt++)
#pragma unroll
        for (int nt = 0; nt < 8; nt++)
#pragma unroll
            for (int j = 0; j < 4; j++) acc[mt][nt][j] = 0.f;

    int am = tid >> 1;
    int ac0 = (tid & 1) * 16;
    int bn = tid >> 1;
    int bco = (tid & 1) * 32;
    const char* w1P = (const char*)g_w1t + (size_t)bn * (NH * 2) + bco;
    uint32_t bD0 = smem_u32(&bH[0][bn][0]) + bco;
    const uint32_t bStride = NA * LDS_A * 2;
    const uint32_t aStride = MT * LDS_A * 2;

    __syncthreads();   // s_win ready

    uint32_t aRow = (uint32_t)(lane & 15);
    uint32_t aCol = (uint32_t)(lane >> 4) * 16u;
    uint32_t bRow = (uint32_t)((lane & 7) + ((lane >> 4) << 3));
    uint32_t bCol = (uint32_t)((lane >> 3) & 1) * 16u;
    uint32_t aBase = smem_u32(&aH[0][0][0]);
    uint32_t bBase = smem_u32(&bH[0][0][0]);

    int wi = s_win[am];
    int ws = wi & 255, we2 = (wi >> 8) & 255, wk = wi >> 16;
    const __half* gbase = g_tab16 + ((size_t)((wk - 1) * NB + b) * NS) * NH + ac0;
    const __half* sRowBase  = gbase + (size_t)ws * NH;
    const __half* e2RowBase = gbase + (size_t)we2 * NH;

    // prologue: B(0) + both rows for t=0
    CP_ASYNC16(bD0,      w1P);
    CP_ASYNC16(bD0 + 16, w1P + 16);
    CP_COMMIT();
    uint4 rsA = *(const uint4*)(sRowBase);
    uint4 rsB = *(const uint4*)(sRowBase + 8);
    uint4 reA = *(const uint4*)(e2RowBase);
    uint4 reB = *(const uint4*)(e2RowBase + 8);

    for (int t = 0; t < NKT; t++) {
        int cur = t & 1, nxt = cur ^ 1;
        bool more = (t + 1 < NKT);

        {
            uint4 r0, r1;
            r0.x = hmax2u(rsA.x, reA.x); r0.y = hmax2u(rsA.y, reA.y);
            r0.z = hmax2u(rsA.z, reA.z); r0.w = hmax2u(rsA.w, reA.w);
            r1.x = hmax2u(rsB.x, reB.x); r1.y = hmax2u(rsB.y, reB.y);
            r1.z = hmax2u(rsB.z, reB.z); r1.w = hmax2u(rsB.w, reB.w);
            *(uint4*)&aH[cur][am][ac0]     = r0;
            *(uint4*)&aH[cur][am][ac0 + 8] = r1;
        }
        if (more) {
            const char* hp = w1P + (t + 1) * (KT * 2);
            uint32_t hd = bD0 + (uint32_t)nxt * bStride;
            CP_ASYNC16(hd,      hp);
            CP_ASYNC16(hd + 16, hp + 16);
            CP_COMMIT();
            CP_WAIT1();
        } else {
            CP_WAIT0();
        }
        __syncthreads();

        if (more) {
            const __half* ps = sRowBase  + (t + 1) * KT;
            const __half* pe = e2RowBase + (t + 1) * KT;
            rsA = *(const uint4*)(ps);
            rsB = *(const uint4*)(ps + 8);
            reA = *(const uint4*)(pe);
            reB = *(const uint4*)(pe + 8);
        }

        uint32_t aB = aBase + (uint32_t)cur * aStride;
        uint32_t bB = bBase + (uint32_t)cur * bStride;
#pragma unroll
        for (int ks = 0; ks < 2; ks++) {
            uint32_t kOff = (uint32_t)ks * 32u;
            uint32_t A[2][4];
#pragma unroll
            for (int mt = 0; mt < 2; mt++) {
                uint32_t row = (uint32_t)(wm * 32 + mt * 16) + aRow;
                uint32_t off = row * (LDS_A * 2) + kOff + aCol;
                LDSM_X4(A[mt][0], A[mt][1], A[mt][2], A[mt][3], aB + off);
            }
#pragma unroll
            for (int np = 0; np < 4; np++) {
                uint32_t nrow = (uint32_t)(wn * 64 + np * 16) + bRow;
                uint32_t off = nrow * (LDS_A * 2) + kOff + bCol;
                uint32_t B[4];
                LDSM_X4(B[0], B[1], B[2], B[3], bB + off);
#pragma unroll
                for (int mt = 0; mt < 2; mt++) {
#pragma unroll
                    for (int h = 0; h < 2; h++) {
                        mma_fp16(acc[mt][np * 2 + h], A[mt], &B[h * 2]);
                    }
                }
            }
        }
    }
    __syncthreads();

    // epilogue: relu(acc + b1) dot W2, reduce over n
    int gq = lane >> 2;
    int gr = lane & 3;
#pragma unroll
    for (int mt = 0; mt < 2; mt++) {
        float p0 = 0.f, p1 = 0.f;
#pragma unroll
        for (int nt = 0; nt < 8; nt++) {
            int col = wn * 64 + nt * 8 + gr * 2;
            float b1a = sb1[col], b1b = sb1[col + 1];
            float w2a = sw2[col], w2b = sw2[col + 1];
            p0 = fmaf(fmaxf(acc[mt][nt][0] + b1a, 0.f), w2a, p0);
            p0 = fmaf(fmaxf(acc[mt][nt][1] + b1b, 0.f), w2b, p0);
            p1 = fmaf(fmaxf(acc[mt][nt][2] + b1a, 0.f), w2a, p1);
            p1 = fmaf(fmaxf(acc[mt][nt][3] + b1b, 0.f), w2b, p1);
        }
#pragma unroll
        for (int off = 1; off <= 2; off <<= 1) {
            p0 += __shfl_xor_sync(0xffffffffu, p0, off);
            p1 += __shfl_xor_sync(0xffffffffu, p1, off);
        }
        if (gr == 0) {
            int row = wm * 32 + mt * 16 + gq;
            sPart[wn][row]     = p0;
            sPart[wn][row + 8] = p1;
        }
    }
    __syncthreads();
    if (tid < MT) {
        int n = n0 + tid;
        if (n < NWIN)
            g_scores[b * NWPAD + n] = sPart[0][tid] + sPart[1][tid];
    }
}

// ---------------------------------------------------------------------------
// Softmax: 32 CTAs, 256 thr. Writes NORMALIZED attn (0 for padded windows).
__global__ void __launch_bounds__(256) k_attn() {
    int b = blockIdx.x;
    int tid = threadIdx.x;
    __shared__ float red[256];

    float mx = -1e30f;
    for (int n = tid; n < NWIN; n += 256)
        mx = fmaxf(mx, g_scores[b * NWPAD + n]);
    red[tid] = mx;
    __syncthreads();
    for (int s = 128; s > 0; s >>= 1) {
        if (tid < s) red[tid] = fmaxf(red[tid], red[tid + s]);
        __syncthreads();
    }
    mx = red[0];
    __syncthreads();
    float sum = 0.f;
    float e[8];
#pragma unroll
    for (int c = 0; c < 8; c++) {
        int n = c * 256 + tid;
        e[c] = (n < NWIN) ? __expf(g_scores[b * NWPAD + n] - mx) : 0.f;
        sum += e[c];
    }
    red[tid] = sum;
    __syncthreads();
    for (int s = 128; s > 0; s >>= 1) {
        if (tid < s) red[tid] += red[tid + s];
        __syncthreads();
    }
    float inv = 1.f / red[0];
#pragma unroll
    for (int c = 0; c < 8; c++) {
        int n = c * 256 + tid;
        if (n < NWPAD) g_attn[b * NWPAD + n] = e[c] * inv;
    }
}

// ---------------------------------------------------------------------------
// Partial weighted sum: grid (NB, NSEG=32), 256 thr, 2 h per thread,
// j unrolled x2 -> MLP 4. Segments span NWPAD; padded windows have attn=0.
__global__ void __launch_bounds__(256) k_out_part(float* __restrict__ out) {
    int b = blockIdx.x;
    int seg = blockIdx.y;
    int tid = threadIdx.x;
    int h0 = tid * 2;
    __shared__ float sattn[WSEG];
    __shared__ int2  soff[WSEG];

    int j0 = seg * WSEG;
    if (tid < WSEG) {
        sattn[tid] = g_attn[b * NWPAD + j0 + tid];
        soff[tid]  = g_woff[j0 + tid];
    }
    __syncthreads();

    const __half* base = g_tab16 + (size_t)b * NS * NH + h0;
    float a0 = 0.f, a1 = 0.f, b0 = 0.f, b1v = 0.f;
#pragma unroll 4
    for (int j = 0; j < WSEG; j += 2) {
        float at0 = sattn[j], at1 = sattn[j + 1];
        int2 o0 = soff[j], o1 = soff[j + 1];
        uint32_t x0 = *(const uint32_t*)(base + o0.x);
        uint32_t y0 = *(const uint32_t*)(base + o0.y);
        uint32_t x1 = *(const uint32_t*)(base + o1.x);
        uint32_t y1 = *(const uint32_t*)(base + o1.y);
        uint32_t m0 = hmax2u(x0, y0);
        uint32_t m1 = hmax2u(x1, y1);
        float2 f0 = __half22float2(*(__half2*)&m0);
        float2 f1 = __half22float2(*(__half2*)&m1);
        a0 = fmaf(at0, f0.x, a0);
        a1 = fmaf(at0, f0.y, a1);
        b0 = fmaf(at1, f1.x, b0);
        b1v = fmaf(at1, f1.y, b1v);
    }
    float* op = out + b * NH + h0;
    atomicAdd(op,     a0 + b0);
    atomicAdd(op + 1, a1 + b1v);
}

// ---------------------------------------------------------------------------
extern "C" void kernel_launch(void* const* d_in, const int* in_sizes, int n_in,
                              void* d_out, int out_size) {
    const float* lstm = (const float*)d_in[0];
    const float* W1   = (const float*)d_in[1];
    const float* b1   = (const float*)d_in[2];
    const float* W2   = (const float*)d_in[3];
    float* out = (float*)d_out;

    k_prep<<<dim3(8, NB + 2), 256>>>(lstm, W1, out);
    k_scores_mma<<<dim3(NWPAD / MT, NB), 256>>>(b1, W2);
    k_attn<<<NB, 256>>>();
    k_out_part<<<dim3(NB, NSEG), 256>>>(out);
}